// round 5
// baseline (speedup 1.0000x reference)
#include <cuda_runtime.h>
#include <cstdint>

#define N   4096
#define D   2048
#define DL  1024
#define BM  128
#define BN  128
#define BK  16
#define NTILE (N / BN)   // 32
#define MARGIN 0.3f
#define EPSC   1e-12f

// ---------------- scratch (no allocations allowed) ----------------
__device__ int   g_tgt[N];
__device__ float g_sq[N];
__device__ float g_lsq[N];
__device__ float g_posVal[NTILE * N];
__device__ int   g_posIdx[NTILE * N];
__device__ float g_negVal[NTILE * N];
__device__ int   g_negIdx[NTILE * N];
__device__ float g_rowLoss[N];
__device__ float g_rowLocal[N];

// ---------------- packed fp32x2 helpers (Blackwell FFMA2) ----------------
__device__ __forceinline__ unsigned long long pack2(float lo, float hi) {
    unsigned long long r;
    asm("mov.b64 %0, {%1, %2};" : "=l"(r) : "r"(__float_as_int(lo)), "r"(__float_as_int(hi)));
    return r;
}
__device__ __forceinline__ void ffma2(unsigned long long& c, unsigned long long a, unsigned long long b) {
    asm("fma.rn.f32x2 %0, %1, %2, %3;" : "=l"(c) : "l"(a), "l"(b), "l"(c));
}
__device__ __forceinline__ float lo32(unsigned long long w) {
    return __int_as_float((int)(unsigned)(w & 0xffffffffull));
}
__device__ __forceinline__ float hi32(unsigned long long w) {
    return __int_as_float((int)(unsigned)(w >> 32));
}

// ---------------- kernel 0: normalize targets (int32 vs int64 autodetect) ----
// View buffer as int32. If targets are int64 little-endian with small values,
// every odd 32-bit word (high half) is zero. If targets are int32, the odd
// words are labels themselves and are nonzero with overwhelming probability.
// Only the first 2048 entries are probed: 2*i+1 <= 4095 int32 words = 16 KB,
// in-bounds for BOTH layouts (int32 buffer is 16 KB, int64 buffer is 32 KB).
__global__ void prep_targets(const int* __restrict__ T32) {
    int f = 0;
    for (int i = threadIdx.x; i < N / 2; i += blockDim.x) f |= T32[2 * i + 1];
    int any = __syncthreads_or(f);
    bool is64 = (any == 0);
    for (int i = threadIdx.x; i < N; i += blockDim.x)
        g_tgt[i] = is64 ? T32[2 * i] : T32[i];
}

// ---------------- kernel 1: row squared norms ----------------
__global__ void norms_kernel(const float* __restrict__ X, const float* __restrict__ XL) {
    int b = blockIdx.x;
    int t = threadIdx.x;
    const float* src;
    int len;
    float* dst;
    if (b < N) { src = X + (size_t)b * D;        len = D;  dst = &g_sq[b]; }
    else       { src = XL + (size_t)(b - N) * DL; len = DL; dst = &g_lsq[b - N]; }
    float s = 0.f;
    for (int k = t * 4; k < len; k += 256 * 4) {
        float4 v = *(const float4*)(src + k);
        s += v.x * v.x + v.y * v.y + v.z * v.z + v.w * v.w;
    }
    __shared__ float red[256];
    red[t] = s;
    __syncthreads();
    for (int off = 128; off > 0; off >>= 1) {
        if (t < off) red[t] += red[t + off];
        __syncthreads();
    }
    if (t == 0) *dst = red[0];
}

// ---------------- kernel 2: tiled Gram + fused row-direction hard mining ----
// Block (bx, by) computes dist tile rows [by*128, +128) x cols [bx*128, +128)
// and mines per-row best over this column tile -> slot bx.
__global__ __launch_bounds__(256, 2)
void gram_mine_kernel(const float* __restrict__ X) {
    int bx = blockIdx.x;  // col tile
    int by = blockIdx.y;  // row tile

    __shared__ float As[BK][BM];
    __shared__ float Bs[BK][BN];
    __shared__ float sqR[BM], sqC[BN];
    __shared__ int   tgtR[BM], tgtC[BN];

    int t  = threadIdx.x;       // 0..255
    int tx = t & 15;            // col group (0..15)
    int ty = t >> 4;            // row group (0..15)
    int rowBase = by * BM;
    int colBase = bx * BN;

    if (t < 128) { sqR[t] = g_sq[rowBase + t]; tgtR[t] = g_tgt[rowBase + t]; }
    else { int q = t - 128; sqC[q] = g_sq[colBase + q]; tgtC[q] = g_tgt[colBase + q]; }

    unsigned long long C2[32];
#pragma unroll
    for (int i = 0; i < 32; i++) C2[i] = 0ull;

    // each thread loads 2 float4 of A and 2 of B per BK step
    int m0 = t >> 2;            // 0..63
    int c0 = (t & 3) * 4;       // 0,4,8,12
    const float* A0 = X + (size_t)(rowBase + m0) * D + c0;
    const float* A1 = A0 + (size_t)64 * D;
    const float* B0 = X + (size_t)(colBase + m0) * D + c0;
    const float* B1 = B0 + (size_t)64 * D;

    float4 pa0 = *(const float4*)(A0);
    float4 pa1 = *(const float4*)(A1);
    float4 pb0 = *(const float4*)(B0);
    float4 pb1 = *(const float4*)(B1);

    for (int kt = 0; kt < D; kt += BK) {
        // store prefetched tile (transposed: As[k][m])
        As[c0 + 0][m0] = pa0.x; As[c0 + 1][m0] = pa0.y;
        As[c0 + 2][m0] = pa0.z; As[c0 + 3][m0] = pa0.w;
        As[c0 + 0][m0 + 64] = pa1.x; As[c0 + 1][m0 + 64] = pa1.y;
        As[c0 + 2][m0 + 64] = pa1.z; As[c0 + 3][m0 + 64] = pa1.w;
        Bs[c0 + 0][m0] = pb0.x; Bs[c0 + 1][m0] = pb0.y;
        Bs[c0 + 2][m0] = pb0.z; Bs[c0 + 3][m0] = pb0.w;
        Bs[c0 + 0][m0 + 64] = pb1.x; Bs[c0 + 1][m0 + 64] = pb1.y;
        Bs[c0 + 2][m0 + 64] = pb1.z; Bs[c0 + 3][m0 + 64] = pb1.w;
        __syncthreads();

        if (kt + BK < D) {
            pa0 = *(const float4*)(A0 + kt + BK);
            pa1 = *(const float4*)(A1 + kt + BK);
            pb0 = *(const float4*)(B0 + kt + BK);
            pb1 = *(const float4*)(B1 + kt + BK);
        }

#pragma unroll
        for (int kk = 0; kk < BK; kk++) {
            float4 a0 = *(const float4*)&As[kk][ty * 8];
            float4 a1 = *(const float4*)&As[kk][ty * 8 + 4];
            float4 b0 = *(const float4*)&Bs[kk][tx * 8];
            float4 b1 = *(const float4*)&Bs[kk][tx * 8 + 4];
            unsigned long long bp0 = pack2(b0.x, b0.y);
            unsigned long long bp1 = pack2(b0.z, b0.w);
            unsigned long long bp2 = pack2(b1.x, b1.y);
            unsigned long long bp3 = pack2(b1.z, b1.w);
            float av[8] = {a0.x, a0.y, a0.z, a0.w, a1.x, a1.y, a1.z, a1.w};
#pragma unroll
            for (int r = 0; r < 8; r++) {
                unsigned long long ap = pack2(av[r], av[r]);
                ffma2(C2[r * 4 + 0], ap, bp0);
                ffma2(C2[r * 4 + 1], ap, bp1);
                ffma2(C2[r * 4 + 2], ap, bp2);
                ffma2(C2[r * 4 + 3], ap, bp3);
            }
        }
        __syncthreads();
    }

    // dist(r, c) from accumulated dot products
    auto distAt = [&](int r, int c) -> float {
        unsigned long long w = C2[r * 4 + (c >> 1)];
        float dot = (c & 1) ? hi32(w) : lo32(w);
        float ds = sqR[ty * 8 + r] + sqC[tx * 8 + c] - 2.f * dot;
        return sqrtf(fmaxf(ds, EPSC));
    };

    // ---- per global row, best over this col tile ----
#pragma unroll
    for (int r = 0; r < 8; r++) {
        int gi = rowBase + ty * 8 + r;
        int ti = tgtR[ty * 8 + r];
        float pv = -1e30f; int pi = 0x7fffffff;
        float nv =  1e30f; int ni = 0x7fffffff;
#pragma unroll
        for (int c = 0; c < 8; c++) {
            int gj = colBase + tx * 8 + c;
            float dv = distAt(r, c);
            if (ti == tgtC[tx * 8 + c]) {
                if (gi != gj && (dv > pv || (dv == pv && gj < pi))) { pv = dv; pi = gj; }
            } else {
                if (dv < nv || (dv == nv && gj < ni)) { nv = dv; ni = gj; }
            }
        }
        // reduce across the 16 tx lanes (two independent 16-lane halves per warp)
        for (int off = 8; off > 0; off >>= 1) {
            float opv = __shfl_xor_sync(0xffffffffu, pv, off);
            int   opi = __shfl_xor_sync(0xffffffffu, pi, off);
            float onv = __shfl_xor_sync(0xffffffffu, nv, off);
            int   oni = __shfl_xor_sync(0xffffffffu, ni, off);
            if (opv > pv || (opv == pv && opi < pi)) { pv = opv; pi = opi; }
            if (onv < nv || (onv == nv && oni < ni)) { nv = onv; ni = oni; }
        }
        if (tx == 0) {
            g_posVal[bx * N + gi] = pv; g_posIdx[bx * N + gi] = pi;
            g_negVal[bx * N + gi] = nv; g_negIdx[bx * N + gi] = ni;
        }
    }
}

// ---------------- kernel 3: combine partials + local distances ----------------
__global__ void finalize_rows(const float* __restrict__ XL) {
    int warp = (blockIdx.x * blockDim.x + threadIdx.x) >> 5;
    int lane = threadIdx.x & 31;
    if (warp >= N) return;
    int row = warp;

    float pv = g_posVal[lane * N + row]; int pi = g_posIdx[lane * N + row];
    float nv = g_negVal[lane * N + row]; int ni = g_negIdx[lane * N + row];
    for (int off = 16; off > 0; off >>= 1) {
        float opv = __shfl_xor_sync(0xffffffffu, pv, off);
        int   opi = __shfl_xor_sync(0xffffffffu, pi, off);
        float onv = __shfl_xor_sync(0xffffffffu, nv, off);
        int   oni = __shfl_xor_sync(0xffffffffu, ni, off);
        if (opv > pv || (opv == pv && opi < pi)) { pv = opv; pi = opi; }
        if (onv < nv || (onv == nv && oni < ni)) { nv = onv; ni = oni; }
    }
    if (pi < 0 || pi >= N) pi = row;  // safety (should never happen)
    if (ni < 0 || ni >= N) ni = row;

    const float* li = XL + (size_t)row * DL;
    const float* lp = XL + (size_t)pi  * DL;
    const float* ln = XL + (size_t)ni  * DL;
    float dp = 0.f, dn = 0.f;
    for (int k = lane * 4; k < DL; k += 128) {
        float4 a = *(const float4*)(li + k);
        float4 b = *(const float4*)(lp + k);
        float4 c = *(const float4*)(ln + k);
        dp += a.x * b.x + a.y * b.y + a.z * b.z + a.w * b.w;
        dn += a.x * c.x + a.y * c.y + a.z * c.z + a.w * c.w;
    }
    for (int off = 16; off > 0; off >>= 1) {
        dp += __shfl_xor_sync(0xffffffffu, dp, off);
        dn += __shfl_xor_sync(0xffffffffu, dn, off);
    }
    if (lane == 0) {
        float lap = sqrtf(fmaxf(g_lsq[row] + g_lsq[pi] - 2.f * dp, EPSC));
        float lan = sqrtf(fmaxf(g_lsq[row] + g_lsq[ni] - 2.f * dn, EPSC));
        g_rowLoss[row]  = fmaxf(0.f, pv - nv + MARGIN);
        g_rowLocal[row] = fmaxf(0.f, lap - lan + MARGIN);
    }
}

// ---------------- kernel 4: deterministic means ----------------
__global__ void final_reduce(float* __restrict__ out, int out_size) {
    __shared__ float s1[256], s2[256];
    int t = threadIdx.x;
    float a = 0.f, b = 0.f;
    for (int i = t; i < N; i += 256) { a += g_rowLoss[i]; b += g_rowLocal[i]; }
    s1[t] = a; s2[t] = b;
    __syncthreads();
    for (int off = 128; off > 0; off >>= 1) {
        if (t < off) { s1[t] += s1[t + off]; s2[t] += s2[t + off]; }
        __syncthreads();
    }
    if (t == 0) {
        out[0] = s1[0] / (float)N;
        if (out_size > 1) out[1] = s2[0] / (float)N;
    }
}

// ---------------- launch ----------------
extern "C" void kernel_launch(void* const* d_in, const int* in_sizes, int n_in,
                              void* d_out, int out_size) {
    const float* X  = (const float*)d_in[0];
    const float* XL = (const float*)d_in[1];
    const int*   T  = (const int*)d_in[2];   // int32 OR int64 — autodetected
    (void)in_sizes; (void)n_in;

    prep_targets<<<1, 1024>>>(T);
    norms_kernel<<<2 * N, 256>>>(X, XL);
    dim3 grid(NTILE, NTILE);
    gram_mine_kernel<<<grid, 256>>>(X);
    finalize_rows<<<N / 8, 256>>>(XL);
    final_reduce<<<1, 256>>>((float*)d_out, out_size);
}

// round 6
// speedup vs baseline: 1.6963x; 1.6963x over previous
#include <cuda_runtime.h>
#include <cstdint>

#define N   4096
#define D   2048
#define DL  1024
#define BM  128
#define BN  128
#define BK  16
#define NTILE (N / BN)   // 32
#define NBLK  (NTILE * (NTILE + 1) / 2)  // 528 triangular tiles
#define MARGIN 0.3f
#define EPSC   1e-12f

// ---------------- scratch (no allocations allowed) ----------------
__device__ int   g_tgt[N];
__device__ float g_sq[N];
__device__ float g_lsq[N];
__device__ float g_posVal[NTILE * N];
__device__ int   g_posIdx[NTILE * N];
__device__ float g_negVal[NTILE * N];
__device__ int   g_negIdx[NTILE * N];
__device__ float g_rowLoss[N];
__device__ float g_rowLocal[N];

// ---------------- packed fp32x2 helpers (Blackwell FFMA2) ----------------
__device__ __forceinline__ unsigned long long pack2(float lo, float hi) {
    unsigned long long r;
    asm("mov.b64 %0, {%1, %2};" : "=l"(r) : "r"(__float_as_int(lo)), "r"(__float_as_int(hi)));
    return r;
}
__device__ __forceinline__ void ffma2(unsigned long long& c, unsigned long long a, unsigned long long b) {
    asm("fma.rn.f32x2 %0, %1, %2, %3;" : "=l"(c) : "l"(a), "l"(b), "l"(c));
}
__device__ __forceinline__ float lo32(unsigned long long w) {
    return __int_as_float((int)(unsigned)(w & 0xffffffffull));
}
__device__ __forceinline__ float hi32(unsigned long long w) {
    return __int_as_float((int)(unsigned)(w >> 32));
}

// ---------------- kernel 0: normalize targets (int32 vs int64 autodetect) ----
__global__ void prep_targets(const int* __restrict__ T32) {
    int f = 0;
    for (int i = threadIdx.x; i < N / 2; i += blockDim.x) f |= T32[2 * i + 1];
    int any = __syncthreads_or(f);
    bool is64 = (any == 0);
    for (int i = threadIdx.x; i < N; i += blockDim.x)
        g_tgt[i] = is64 ? T32[2 * i] : T32[i];
}

// ---------------- kernel 1: row squared norms ----------------
__global__ void norms_kernel(const float* __restrict__ X, const float* __restrict__ XL) {
    int b = blockIdx.x;
    int t = threadIdx.x;
    const float* src;
    int len;
    float* dst;
    if (b < N) { src = X + (size_t)b * D;        len = D;  dst = &g_sq[b]; }
    else       { src = XL + (size_t)(b - N) * DL; len = DL; dst = &g_lsq[b - N]; }
    float s = 0.f;
    for (int k = t * 4; k < len; k += 256 * 4) {
        float4 v = *(const float4*)(src + k);
        s += v.x * v.x + v.y * v.y + v.z * v.z + v.w * v.w;
    }
    __shared__ float red[256];
    red[t] = s;
    __syncthreads();
    for (int off = 128; off > 0; off >>= 1) {
        if (t < off) red[t] += red[t + off];
        __syncthreads();
    }
    if (t == 0) *dst = red[0];
}

// ---------------- kernel 2: triangular tiled Gram + fused dual mining ------
// Linear block k -> (bx, by) with by <= bx (upper triangle incl. diagonal).
// Row-direction mining writes slot bx for rows of tile by.
// Col-direction mining (off-diag only) writes slot by for rows of tile bx.
// Every (slot, row) pair has exactly one writer.
__global__ __launch_bounds__(256, 2)
void gram_mine_kernel(const float* __restrict__ X) {
    // decode triangular index: bx = largest with bx*(bx+1)/2 <= k
    int kblk = blockIdx.x;
    int bx = (int)((sqrtf(8.0f * (float)kblk + 1.0f) - 1.0f) * 0.5f);
    while (bx * (bx + 1) / 2 > kblk) bx--;
    while ((bx + 1) * (bx + 2) / 2 <= kblk) bx++;
    int by = kblk - bx * (bx + 1) / 2;   // 0..bx

    __shared__ float As[BK][BM];
    __shared__ float Bs[BK][BN];
    __shared__ float sqR[BM], sqC[BN];
    __shared__ int   tgtR[BM], tgtC[BN];
    __shared__ float redV[16][128];
    __shared__ int   redI[16][128];

    int t  = threadIdx.x;       // 0..255
    int tx = t & 15;            // col group (0..15)
    int ty = t >> 4;            // row group (0..15)
    int rowBase = by * BM;
    int colBase = bx * BN;

    if (t < 128) { sqR[t] = g_sq[rowBase + t]; tgtR[t] = g_tgt[rowBase + t]; }
    else { int q = t - 128; sqC[q] = g_sq[colBase + q]; tgtC[q] = g_tgt[colBase + q]; }

    unsigned long long C2[32];
#pragma unroll
    for (int i = 0; i < 32; i++) C2[i] = 0ull;

    // each thread loads 2 float4 of A and 2 of B per BK step
    int m0 = t >> 2;            // 0..63
    int c0 = (t & 3) * 4;       // 0,4,8,12
    const float* A0 = X + (size_t)(rowBase + m0) * D + c0;
    const float* A1 = A0 + (size_t)64 * D;
    const float* B0 = X + (size_t)(colBase + m0) * D + c0;
    const float* B1 = B0 + (size_t)64 * D;

    float4 pa0 = *(const float4*)(A0);
    float4 pa1 = *(const float4*)(A1);
    float4 pb0 = *(const float4*)(B0);
    float4 pb1 = *(const float4*)(B1);

    for (int kt = 0; kt < D; kt += BK) {
        // store prefetched tile (transposed: As[k][m])
        As[c0 + 0][m0] = pa0.x; As[c0 + 1][m0] = pa0.y;
        As[c0 + 2][m0] = pa0.z; As[c0 + 3][m0] = pa0.w;
        As[c0 + 0][m0 + 64] = pa1.x; As[c0 + 1][m0 + 64] = pa1.y;
        As[c0 + 2][m0 + 64] = pa1.z; As[c0 + 3][m0 + 64] = pa1.w;
        Bs[c0 + 0][m0] = pb0.x; Bs[c0 + 1][m0] = pb0.y;
        Bs[c0 + 2][m0] = pb0.z; Bs[c0 + 3][m0] = pb0.w;
        Bs[c0 + 0][m0 + 64] = pb1.x; Bs[c0 + 1][m0 + 64] = pb1.y;
        Bs[c0 + 2][m0 + 64] = pb1.z; Bs[c0 + 3][m0 + 64] = pb1.w;
        __syncthreads();

        if (kt + BK < D) {
            pa0 = *(const float4*)(A0 + kt + BK);
            pa1 = *(const float4*)(A1 + kt + BK);
            pb0 = *(const float4*)(B0 + kt + BK);
            pb1 = *(const float4*)(B1 + kt + BK);
        }

#pragma unroll
        for (int kk = 0; kk < BK; kk++) {
            float4 a0 = *(const float4*)&As[kk][ty * 8];
            float4 a1 = *(const float4*)&As[kk][ty * 8 + 4];
            // B pairs loaded directly in packed f32x2 form (no mov.b64 packs)
            ulonglong2 bq0 = *(const ulonglong2*)&Bs[kk][tx * 8];
            ulonglong2 bq1 = *(const ulonglong2*)&Bs[kk][tx * 8 + 4];
            float av[8] = {a0.x, a0.y, a0.z, a0.w, a1.x, a1.y, a1.z, a1.w};
#pragma unroll
            for (int r = 0; r < 8; r++) {
                unsigned long long ap = pack2(av[r], av[r]);
                ffma2(C2[r * 4 + 0], ap, bq0.x);
                ffma2(C2[r * 4 + 1], ap, bq0.y);
                ffma2(C2[r * 4 + 2], ap, bq1.x);
                ffma2(C2[r * 4 + 3], ap, bq1.y);
            }
        }
        __syncthreads();
    }

    // dist(r, c) from accumulated dot products
    auto distAt = [&](int r, int c) -> float {
        unsigned long long w = C2[r * 4 + (c >> 1)];
        float dot = (c & 1) ? hi32(w) : lo32(w);
        float ds = sqR[ty * 8 + r] + sqC[tx * 8 + c] - 2.f * dot;
        return sqrtf(fmaxf(ds, EPSC));
    };

    // ---- row direction: per row of tile by, best over this col tile -> slot bx
#pragma unroll
    for (int r = 0; r < 8; r++) {
        int gi = rowBase + ty * 8 + r;
        int ti = tgtR[ty * 8 + r];
        float pv = -1e30f; int pi = 0x7fffffff;
        float nv =  1e30f; int ni = 0x7fffffff;
#pragma unroll
        for (int c = 0; c < 8; c++) {
            int gj = colBase + tx * 8 + c;
            float dv = distAt(r, c);
            if (ti == tgtC[tx * 8 + c]) {
                if (gi != gj && (dv > pv || (dv == pv && gj < pi))) { pv = dv; pi = gj; }
            } else {
                if (dv < nv || (dv == nv && gj < ni)) { nv = dv; ni = gj; }
            }
        }
        for (int off = 8; off > 0; off >>= 1) {
            float opv = __shfl_xor_sync(0xffffffffu, pv, off);
            int   opi = __shfl_xor_sync(0xffffffffu, pi, off);
            float onv = __shfl_xor_sync(0xffffffffu, nv, off);
            int   oni = __shfl_xor_sync(0xffffffffu, ni, off);
            if (opv > pv || (opv == pv && opi < pi)) { pv = opv; pi = opi; }
            if (onv < nv || (onv == nv && oni < ni)) { nv = onv; ni = oni; }
        }
        if (tx == 0) {
            g_posVal[bx * N + gi] = pv; g_posIdx[bx * N + gi] = pi;
            g_negVal[bx * N + gi] = nv; g_negIdx[bx * N + gi] = ni;
        }
    }

    // ---- col direction (off-diagonal only): rows of tile bx, cands tile by -> slot by
    if (by != bx) {
        // POS pass
#pragma unroll
        for (int c = 0; c < 8; c++) {
            int tj = tgtC[tx * 8 + c];
            float pv = -1e30f; int pi = 0x7fffffff;
#pragma unroll
            for (int r = 0; r < 8; r++) {
                int gi = rowBase + ty * 8 + r;
                float dv = distAt(r, c);
                if (tj == tgtR[ty * 8 + r]) {
                    if (dv > pv || (dv == pv && gi < pi)) { pv = dv; pi = gi; }
                }
            }
            redV[ty][tx * 8 + c] = pv; redI[ty][tx * 8 + c] = pi;
        }
        __syncthreads();
        if (t < 128) {
            float pv = -1e30f; int pi = 0x7fffffff;
            for (int y = 0; y < 16; y++) {
                float v = redV[y][t]; int id = redI[y][t];
                if (v > pv || (v == pv && id < pi)) { pv = v; pi = id; }
            }
            g_posVal[by * N + colBase + t] = pv;
            g_posIdx[by * N + colBase + t] = pi;
        }
        __syncthreads();
        // NEG pass
#pragma unroll
        for (int c = 0; c < 8; c++) {
            int tj = tgtC[tx * 8 + c];
            float nv = 1e30f; int ni = 0x7fffffff;
#pragma unroll
            for (int r = 0; r < 8; r++) {
                int gi = rowBase + ty * 8 + r;
                float dv = distAt(r, c);
                if (tj != tgtR[ty * 8 + r]) {
                    if (dv < nv || (dv == nv && gi < ni)) { nv = dv; ni = gi; }
                }
            }
            redV[ty][tx * 8 + c] = nv; redI[ty][tx * 8 + c] = ni;
        }
        __syncthreads();
        if (t < 128) {
            float nv = 1e30f; int ni = 0x7fffffff;
            for (int y = 0; y < 16; y++) {
                float v = redV[y][t]; int id = redI[y][t];
                if (v < nv || (v == nv && id < ni)) { nv = v; ni = id; }
            }
            g_negVal[by * N + colBase + t] = nv;
            g_negIdx[by * N + colBase + t] = ni;
        }
    }
}

// ---------------- kernel 3: combine partials + local distances ----------------
__global__ void finalize_rows(const float* __restrict__ XL) {
    int warp = (blockIdx.x * blockDim.x + threadIdx.x) >> 5;
    int lane = threadIdx.x & 31;
    if (warp >= N) return;
    int row = warp;

    float pv = g_posVal[lane * N + row]; int pi = g_posIdx[lane * N + row];
    float nv = g_negVal[lane * N + row]; int ni = g_negIdx[lane * N + row];
    for (int off = 16; off > 0; off >>= 1) {
        float opv = __shfl_xor_sync(0xffffffffu, pv, off);
        int   opi = __shfl_xor_sync(0xffffffffu, pi, off);
        float onv = __shfl_xor_sync(0xffffffffu, nv, off);
        int   oni = __shfl_xor_sync(0xffffffffu, ni, off);
        if (opv > pv || (opv == pv && opi < pi)) { pv = opv; pi = opi; }
        if (onv < nv || (onv == nv && oni < ni)) { nv = onv; ni = oni; }
    }
    if (pi < 0 || pi >= N) pi = row;  // safety (should never happen)
    if (ni < 0 || ni >= N) ni = row;

    const float* li = XL + (size_t)row * DL;
    const float* lp = XL + (size_t)pi  * DL;
    const float* ln = XL + (size_t)ni  * DL;
    float dp = 0.f, dn = 0.f;
    for (int k = lane * 4; k < DL; k += 128) {
        float4 a = *(const float4*)(li + k);
        float4 b = *(const float4*)(lp + k);
        float4 c = *(const float4*)(ln + k);
        dp += a.x * b.x + a.y * b.y + a.z * b.z + a.w * b.w;
        dn += a.x * c.x + a.y * c.y + a.z * c.z + a.w * c.w;
    }
    for (int off = 16; off > 0; off >>= 1) {
        dp += __shfl_xor_sync(0xffffffffu, dp, off);
        dn += __shfl_xor_sync(0xffffffffu, dn, off);
    }
    if (lane == 0) {
        float lap = sqrtf(fmaxf(g_lsq[row] + g_lsq[pi] - 2.f * dp, EPSC));
        float lan = sqrtf(fmaxf(g_lsq[row] + g_lsq[ni] - 2.f * dn, EPSC));
        g_rowLoss[row]  = fmaxf(0.f, pv - nv + MARGIN);
        g_rowLocal[row] = fmaxf(0.f, lap - lan + MARGIN);
    }
}

// ---------------- kernel 4: deterministic means ----------------
__global__ void final_reduce(float* __restrict__ out, int out_size) {
    __shared__ float s1[256], s2[256];
    int t = threadIdx.x;
    float a = 0.f, b = 0.f;
    for (int i = t; i < N; i += 256) { a += g_rowLoss[i]; b += g_rowLocal[i]; }
    s1[t] = a; s2[t] = b;
    __syncthreads();
    for (int off = 128; off > 0; off >>= 1) {
        if (t < off) { s1[t] += s1[t + off]; s2[t] += s2[t + off]; }
        __syncthreads();
    }
    if (t == 0) {
        out[0] = s1[0] / (float)N;
        if (out_size > 1) out[1] = s2[0] / (float)N;
    }
}

// ---------------- launch ----------------
extern "C" void kernel_launch(void* const* d_in, const int* in_sizes, int n_in,
                              void* d_out, int out_size) {
    const float* X  = (const float*)d_in[0];
    const float* XL = (const float*)d_in[1];
    const int*   T  = (const int*)d_in[2];   // int32 OR int64 — autodetected
    (void)in_sizes; (void)n_in;

    prep_targets<<<1, 1024>>>(T);
    norms_kernel<<<2 * N, 256>>>(X, XL);
    gram_mine_kernel<<<NBLK, 256>>>(X);
    finalize_rows<<<N / 8, 256>>>(XL);
    final_reduce<<<1, 256>>>((float*)d_out, out_size);
}

// round 7
// speedup vs baseline: 2.1456x; 1.2649x over previous
#include <cuda_runtime.h>
#include <cstdint>

#define N   4096
#define D   2048
#define DL  1024
#define BM  128
#define BN  128
#define BK  16
#define NTILE (N / BN)   // 32
#define NBLK  (NTILE * (NTILE + 1) / 2)  // 528 triangular tiles
#define RS_A  132        // As row stride in words (2-way store conflicts, aligned loads)
#define GS_B  12         // Bs column-group stride in words (conflict-free loads)
#define RS_B  200        // Bs row stride in words (16 groups * 12 + pad, 16B-aligned)
#define MARGIN 0.3f
#define EPSC   1e-12f

// ---------------- scratch (no allocations allowed) ----------------
__device__ int   g_tgt[N];
__device__ float g_sq[N];
__device__ float g_lsq[N];
__device__ float g_posVal[NTILE * N];
__device__ int   g_posIdx[NTILE * N];
__device__ float g_negVal[NTILE * N];
__device__ int   g_negIdx[NTILE * N];
__device__ float g_rowLoss[N];
__device__ float g_rowLocal[N];

// ---------------- packed fp32x2 helpers (Blackwell FFMA2) ----------------
__device__ __forceinline__ unsigned long long pack2b(float v) {
    unsigned long long r;
    asm("mov.b64 %0, {%1, %1};" : "=l"(r) : "r"(__float_as_int(v)));
    return r;
}
__device__ __forceinline__ void ffma2(unsigned long long& c, unsigned long long a, unsigned long long b) {
    asm("fma.rn.f32x2 %0, %1, %2, %3;" : "=l"(c) : "l"(a), "l"(b), "l"(c));
}
__device__ __forceinline__ float lo32(unsigned long long w) {
    return __int_as_float((int)(unsigned)(w & 0xffffffffull));
}
__device__ __forceinline__ float hi32(unsigned long long w) {
    return __int_as_float((int)(unsigned)(w >> 32));
}

// ---------------- kernel 0: normalize targets (int32 vs int64 autodetect) ----
__global__ void prep_targets(const int* __restrict__ T32) {
    int f = 0;
    for (int i = threadIdx.x; i < N / 2; i += blockDim.x) f |= T32[2 * i + 1];
    int any = __syncthreads_or(f);
    bool is64 = (any == 0);
    for (int i = threadIdx.x; i < N; i += blockDim.x)
        g_tgt[i] = is64 ? T32[2 * i] : T32[i];
}

// ---------------- kernel 1: row squared norms ----------------
__global__ void norms_kernel(const float* __restrict__ X, const float* __restrict__ XL) {
    int b = blockIdx.x;
    int t = threadIdx.x;
    const float* src;
    int len;
    float* dst;
    if (b < N) { src = X + (size_t)b * D;        len = D;  dst = &g_sq[b]; }
    else       { src = XL + (size_t)(b - N) * DL; len = DL; dst = &g_lsq[b - N]; }
    float s = 0.f;
    for (int k = t * 4; k < len; k += 256 * 4) {
        float4 v = *(const float4*)(src + k);
        s += v.x * v.x + v.y * v.y + v.z * v.z + v.w * v.w;
    }
    __shared__ float red[256];
    red[t] = s;
    __syncthreads();
    for (int off = 128; off > 0; off >>= 1) {
        if (t < off) red[t] += red[t + off];
        __syncthreads();
    }
    if (t == 0) *dst = red[0];
}

// ---------------- kernel 2: triangular tiled Gram + fused dual mining ------
// 128 threads, 128x128 tile, each thread 16(M, packed pairs) x 8(N) outputs.
__global__ __launch_bounds__(128, 2)
void gram_mine_kernel(const float* __restrict__ X) {
    // decode triangular index: bx = largest with bx*(bx+1)/2 <= k
    int kblk = blockIdx.x;
    int bx = (int)((sqrtf(8.0f * (float)kblk + 1.0f) - 1.0f) * 0.5f);
    while (bx * (bx + 1) / 2 > kblk) bx--;
    while ((bx + 1) * (bx + 2) / 2 <= kblk) bx++;
    int by = kblk - bx * (bx + 1) / 2;   // 0..bx

    __shared__ float As[BK * RS_A];      // [k][m], m-stride 1, k-stride 132
    __shared__ float Bs[BK * RS_B];      // [k][group*12 + (c&7)]
    __shared__ float sqR[BM], sqC[BN];
    __shared__ int   tgtR[BM], tgtC[BN];
    __shared__ float redV[8][128];
    __shared__ int   redI[8][128];

    int t  = threadIdx.x;       // 0..127
    int tx = t & 15;            // col group (0..15), 8 cols each
    int ty = t >> 4;            // row group (0..7), 16 rows each
    int rowBase = by * BM;
    int colBase = bx * BN;

    sqR[t] = g_sq[rowBase + t]; tgtR[t] = g_tgt[rowBase + t];
    sqC[t] = g_sq[colBase + t]; tgtC[t] = g_tgt[colBase + t];

    unsigned long long C2[64];   // [pair p 0..7][col c 0..7]
#pragma unroll
    for (int i = 0; i < 64; i++) C2[i] = 0ull;

    // gmem load mapping: m0 = t>>2 (0..31), rows m0+32q; c0 = (t&3)*4
    int m0 = t >> 2;
    int c0 = (t & 3) * 4;
    const float* Ap[4];
    const float* Bp[4];
#pragma unroll
    for (int q = 0; q < 4; q++) {
        Ap[q] = X + (size_t)(rowBase + m0 + 32 * q) * D + c0;
        Bp[q] = X + (size_t)(colBase + m0 + 32 * q) * D + c0;
    }
    // precomputed B smem group offsets for the 4 rows this thread stores
    int bgo[4];
#pragma unroll
    for (int q = 0; q < 4; q++) {
        int m = m0 + 32 * q;
        bgo[q] = (m >> 3) * GS_B + (m & 7);
    }

    float4 pa[4], pb[4];
#pragma unroll
    for (int q = 0; q < 4; q++) { pa[q] = *(const float4*)(Ap[q]); pb[q] = *(const float4*)(Bp[q]); }

    for (int kt = 0; kt < D; kt += BK) {
#pragma unroll
        for (int q = 0; q < 4; q++) {
            int m = m0 + 32 * q;
            As[(c0 + 0) * RS_A + m] = pa[q].x;
            As[(c0 + 1) * RS_A + m] = pa[q].y;
            As[(c0 + 2) * RS_A + m] = pa[q].z;
            As[(c0 + 3) * RS_A + m] = pa[q].w;
            Bs[(c0 + 0) * RS_B + bgo[q]] = pb[q].x;
            Bs[(c0 + 1) * RS_B + bgo[q]] = pb[q].y;
            Bs[(c0 + 2) * RS_B + bgo[q]] = pb[q].z;
            Bs[(c0 + 3) * RS_B + bgo[q]] = pb[q].w;
        }
        __syncthreads();

        if (kt + BK < D) {
#pragma unroll
            for (int q = 0; q < 4; q++) {
                pa[q] = *(const float4*)(Ap[q] + kt + BK);
                pb[q] = *(const float4*)(Bp[q] + kt + BK);
            }
        }

#pragma unroll
        for (int kk = 0; kk < BK; kk++) {
            const float* Ab = &As[kk * RS_A + ty * 16];
            ulonglong2 aq0 = *(const ulonglong2*)(Ab);       // pairs 0,1
            ulonglong2 aq1 = *(const ulonglong2*)(Ab + 4);   // pairs 2,3
            ulonglong2 aq2 = *(const ulonglong2*)(Ab + 8);   // pairs 4,5
            ulonglong2 aq3 = *(const ulonglong2*)(Ab + 12);  // pairs 6,7
            const float* Bb = &Bs[kk * RS_B + tx * GS_B];
            float4 b0 = *(const float4*)(Bb);
            float4 b1 = *(const float4*)(Bb + 4);
            unsigned long long ar[8] = {aq0.x, aq0.y, aq1.x, aq1.y,
                                        aq2.x, aq2.y, aq3.x, aq3.y};
            unsigned long long bb[8] = {pack2b(b0.x), pack2b(b0.y), pack2b(b0.z), pack2b(b0.w),
                                        pack2b(b1.x), pack2b(b1.y), pack2b(b1.z), pack2b(b1.w)};
#pragma unroll
            for (int p = 0; p < 8; p++) {
#pragma unroll
                for (int c = 0; c < 8; c++) ffma2(C2[p * 8 + c], ar[p], bb[c]);
            }
        }
        __syncthreads();
    }

    // dist(r, c): r 0..15 local rows, c 0..7 local cols
    auto distAt = [&](int r, int c) -> float {
        unsigned long long w = C2[(r >> 1) * 8 + c];
        float dot = (r & 1) ? hi32(w) : lo32(w);
        float ds = sqR[ty * 16 + r] + sqC[tx * 8 + c] - 2.f * dot;
        return sqrtf(fmaxf(ds, EPSC));
    };

    // ---- row direction: rows of tile by, best over this col tile -> slot bx
#pragma unroll
    for (int r = 0; r < 16; r++) {
        int gi = rowBase + ty * 16 + r;
        int ti = tgtR[ty * 16 + r];
        float pv = -1e30f; int pi = 0x7fffffff;
        float nv =  1e30f; int ni = 0x7fffffff;
#pragma unroll
        for (int c = 0; c < 8; c++) {
            int gj = colBase + tx * 8 + c;
            float dv = distAt(r, c);
            if (ti == tgtC[tx * 8 + c]) {
                if (gi != gj && (dv > pv || (dv == pv && gj < pi))) { pv = dv; pi = gj; }
            } else {
                if (dv < nv || (dv == nv && gj < ni)) { nv = dv; ni = gj; }
            }
        }
        for (int off = 8; off > 0; off >>= 1) {
            float opv = __shfl_xor_sync(0xffffffffu, pv, off);
            int   opi = __shfl_xor_sync(0xffffffffu, pi, off);
            float onv = __shfl_xor_sync(0xffffffffu, nv, off);
            int   oni = __shfl_xor_sync(0xffffffffu, ni, off);
            if (opv > pv || (opv == pv && opi < pi)) { pv = opv; pi = opi; }
            if (onv < nv || (onv == nv && oni < ni)) { nv = onv; ni = oni; }
        }
        if (tx == 0) {
            g_posVal[bx * N + gi] = pv; g_posIdx[bx * N + gi] = pi;
            g_negVal[bx * N + gi] = nv; g_negIdx[bx * N + gi] = ni;
        }
    }

    // ---- col direction (off-diagonal only): cols of tile bx, cands tile by -> slot by
    if (by != bx) {
        // POS pass
#pragma unroll
        for (int c = 0; c < 8; c++) {
            int tj = tgtC[tx * 8 + c];
            float pv = -1e30f; int pi = 0x7fffffff;
#pragma unroll
            for (int r = 0; r < 16; r++) {
                int gi = rowBase + ty * 16 + r;
                float dv = distAt(r, c);
                if (tj == tgtR[ty * 16 + r]) {
                    if (dv > pv || (dv == pv && gi < pi)) { pv = dv; pi = gi; }
                }
            }
            redV[ty][tx * 8 + c] = pv; redI[ty][tx * 8 + c] = pi;
        }
        __syncthreads();
        {
            float pv = -1e30f; int pi = 0x7fffffff;
#pragma unroll
            for (int y = 0; y < 8; y++) {
                float v = redV[y][t]; int id = redI[y][t];
                if (v > pv || (v == pv && id < pi)) { pv = v; pi = id; }
            }
            g_posVal[by * N + colBase + t] = pv;
            g_posIdx[by * N + colBase + t] = pi;
        }
        __syncthreads();
        // NEG pass
#pragma unroll
        for (int c = 0; c < 8; c++) {
            int tj = tgtC[tx * 8 + c];
            float nv = 1e30f; int ni = 0x7fffffff;
#pragma unroll
            for (int r = 0; r < 16; r++) {
                int gi = rowBase + ty * 16 + r;
                float dv = distAt(r, c);
                if (tj != tgtR[ty * 16 + r]) {
                    if (dv < nv || (dv == nv && gi < ni)) { nv = dv; ni = gi; }
                }
            }
            redV[ty][tx * 8 + c] = nv; redI[ty][tx * 8 + c] = ni;
        }
        __syncthreads();
        {
            float nv = 1e30f; int ni = 0x7fffffff;
#pragma unroll
            for (int y = 0; y < 8; y++) {
                float v = redV[y][t]; int id = redI[y][t];
                if (v < nv || (v == nv && id < ni)) { nv = v; ni = id; }
            }
            g_negVal[by * N + colBase + t] = nv;
            g_negIdx[by * N + colBase + t] = ni;
        }
    }
}

// ---------------- kernel 3: combine partials + local distances ----------------
__global__ void finalize_rows(const float* __restrict__ XL) {
    int warp = (blockIdx.x * blockDim.x + threadIdx.x) >> 5;
    int lane = threadIdx.x & 31;
    if (warp >= N) return;
    int row = warp;

    float pv = g_posVal[lane * N + row]; int pi = g_posIdx[lane * N + row];
    float nv = g_negVal[lane * N + row]; int ni = g_negIdx[lane * N + row];
    for (int off = 16; off > 0; off >>= 1) {
        float opv = __shfl_xor_sync(0xffffffffu, pv, off);
        int   opi = __shfl_xor_sync(0xffffffffu, pi, off);
        float onv = __shfl_xor_sync(0xffffffffu, nv, off);
        int   oni = __shfl_xor_sync(0xffffffffu, ni, off);
        if (opv > pv || (opv == pv && opi < pi)) { pv = opv; pi = opi; }
        if (onv < nv || (onv == nv && oni < ni)) { nv = onv; ni = oni; }
    }
    if (pi < 0 || pi >= N) pi = row;  // safety (should never happen)
    if (ni < 0 || ni >= N) ni = row;

    const float* li = XL + (size_t)row * DL;
    const float* lp = XL + (size_t)pi  * DL;
    const float* ln = XL + (size_t)ni  * DL;
    float dp = 0.f, dn = 0.f;
    for (int k = lane * 4; k < DL; k += 128) {
        float4 a = *(const float4*)(li + k);
        float4 b = *(const float4*)(lp + k);
        float4 c = *(const float4*)(ln + k);
        dp += a.x * b.x + a.y * b.y + a.z * b.z + a.w * b.w;
        dn += a.x * c.x + a.y * c.y + a.z * c.z + a.w * c.w;
    }
    for (int off = 16; off > 0; off >>= 1) {
        dp += __shfl_xor_sync(0xffffffffu, dp, off);
        dn += __shfl_xor_sync(0xffffffffu, dn, off);
    }
    if (lane == 0) {
        float lap = sqrtf(fmaxf(g_lsq[row] + g_lsq[pi] - 2.f * dp, EPSC));
        float lan = sqrtf(fmaxf(g_lsq[row] + g_lsq[ni] - 2.f * dn, EPSC));
        g_rowLoss[row]  = fmaxf(0.f, pv - nv + MARGIN);
        g_rowLocal[row] = fmaxf(0.f, lap - lan + MARGIN);
    }
}

// ---------------- kernel 4: deterministic means ----------------
__global__ void final_reduce(float* __restrict__ out, int out_size) {
    __shared__ float s1[256], s2[256];
    int t = threadIdx.x;
    float a = 0.f, b = 0.f;
    for (int i = t; i < N; i += 256) { a += g_rowLoss[i]; b += g_rowLocal[i]; }
    s1[t] = a; s2[t] = b;
    __syncthreads();
    for (int off = 128; off > 0; off >>= 1) {
        if (t < off) { s1[t] += s1[t + off]; s2[t] += s2[t + off]; }
        __syncthreads();
    }
    if (t == 0) {
        out[0] = s1[0] / (float)N;
        if (out_size > 1) out[1] = s2[0] / (float)N;
    }
}

// ---------------- launch ----------------
extern "C" void kernel_launch(void* const* d_in, const int* in_sizes, int n_in,
                              void* d_out, int out_size) {
    const float* X  = (const float*)d_in[0];
    const float* XL = (const float*)d_in[1];
    const int*   T  = (const int*)d_in[2];   // int32 OR int64 — autodetected
    (void)in_sizes; (void)n_in;

    prep_targets<<<1, 1024>>>(T);
    norms_kernel<<<2 * N, 256>>>(X, XL);
    gram_mine_kernel<<<NBLK, 128>>>(X);
    finalize_rows<<<N / 8, 256>>>(XL);
    final_reduce<<<1, 256>>>((float*)d_out, out_size);
}

// round 9
// speedup vs baseline: 3.5885x; 1.6725x over previous
#include <cuda_runtime.h>
#include <cuda_bf16.h>
#include <cstdint>

#define N    4096
#define D    2048
#define DL   1024
#define BM   128
#define BN   128
#define KS   32                  // k elems per pipeline stage
#define NSTG (D / KS)            // 64
#define NTILE (N / BN)           // 32
#define NBLK  (NTILE * (NTILE + 1) / 2)  // 528
#define TILE_B   4096            // one 128x16 bf16 sub-tile
#define STAGE_B  (8 * TILE_B)    // {Ahi,Alo,Bhi,Blo} x {k0-15,k16-31} = 32 KB
#define DYN_B    (2 * STAGE_B)   // 64 KB double buffer
#define MARGIN 0.3f
#define EPSC   1e-12f

// ---------------- scratch (no allocations allowed) ----------------
__device__ int   g_tgt[N];
__device__ float g_sq[N];
__device__ float g_lsq[N];
__device__ __nv_bfloat16 g_xhi[(size_t)N * D];
__device__ __nv_bfloat16 g_xlo[(size_t)N * D];
__device__ float g_posVal[NTILE * N];
__device__ int   g_posIdx[NTILE * N];
__device__ float g_negVal[NTILE * N];
__device__ int   g_negIdx[NTILE * N];
__device__ float g_rowLoss[N];
__device__ float g_rowLocal[N];

// ---------------- helpers ----------------
__device__ __forceinline__ unsigned smem_u32(const void* p) {
    unsigned a;
    asm("{ .reg .u64 t; cvta.to.shared.u64 t, %1; cvt.u32.u64 %0, t; }" : "=r"(a) : "l"(p));
    return a;
}
__device__ __forceinline__ void cp16(unsigned dst, const void* src) {
    asm volatile("cp.async.cg.shared.global [%0], [%1], 16;" :: "r"(dst), "l"(src) : "memory");
}
__device__ __forceinline__ void ldsm4(unsigned* r, unsigned addr) {
    asm volatile("ldmatrix.sync.aligned.m8n8.x4.shared.b16 {%0,%1,%2,%3}, [%4];"
        : "=r"(r[0]), "=r"(r[1]), "=r"(r[2]), "=r"(r[3]) : "r"(addr));
}
__device__ __forceinline__ void mma16816(float* c, const unsigned* a, unsigned b0, unsigned b1) {
    asm volatile("mma.sync.aligned.m16n8k16.row.col.f32.bf16.bf16.f32 "
        "{%0,%1,%2,%3}, {%4,%5,%6,%7}, {%8,%9}, {%0,%1,%2,%3};"
        : "+f"(c[0]), "+f"(c[1]), "+f"(c[2]), "+f"(c[3])
        : "r"(a[0]), "r"(a[1]), "r"(a[2]), "r"(a[3]), "r"(b0), "r"(b1));
}
// swizzled offset within a 128x16 bf16 tile: row r (0..127), 16B half h (0..1)
__device__ __forceinline__ unsigned tswz(int r, int h) {
    return (unsigned)(r * 32 + ((h * 16) ^ ((r & 4) << 2)));
}

// ---------------- kernel 0: normalize targets (int32 vs int64 autodetect) ----
__global__ void prep_targets(const int* __restrict__ T32) {
    int f = 0;
    for (int i = threadIdx.x; i < N / 2; i += blockDim.x) f |= T32[2 * i + 1];
    int any = __syncthreads_or(f);
    bool is64 = (any == 0);
    for (int i = threadIdx.x; i < N; i += blockDim.x)
        g_tgt[i] = is64 ? T32[2 * i] : T32[i];
}

// ---------------- kernel 1: split X into bf16 hi/lo + row norms -------------
__global__ void convert_kernel(const float* __restrict__ X) {
    int row = blockIdx.x;
    int t = threadIdx.x;
    const float* src = X + (size_t)row * D;
    float s = 0.f;
    for (int k = t * 4; k < D; k += 256 * 4) {
        float4 v = *(const float4*)(src + k);
        s += v.x * v.x + v.y * v.y + v.z * v.z + v.w * v.w;
        float xs[4] = {v.x, v.y, v.z, v.w};
        unsigned hb[4], lb[4];
#pragma unroll
        for (int i = 0; i < 4; i++) {
            __nv_bfloat16 h = __float2bfloat16(xs[i]);
            __nv_bfloat16 l = __float2bfloat16(xs[i] - __bfloat162float(h));
            hb[i] = (unsigned)__bfloat16_as_ushort(h);
            lb[i] = (unsigned)__bfloat16_as_ushort(l);
        }
        *(uint2*)&g_xhi[(size_t)row * D + k] = make_uint2(hb[0] | (hb[1] << 16), hb[2] | (hb[3] << 16));
        *(uint2*)&g_xlo[(size_t)row * D + k] = make_uint2(lb[0] | (lb[1] << 16), lb[2] | (lb[3] << 16));
    }
    __shared__ float red[256];
    red[t] = s;
    __syncthreads();
    for (int off = 128; off > 0; off >>= 1) {
        if (t < off) red[t] += red[t + off];
        __syncthreads();
    }
    if (t == 0) g_sq[row] = red[0];
}

// ---------------- kernel 1b: local-feature row norms ------------------------
__global__ void lnorms_kernel(const float* __restrict__ XL) {
    int b = blockIdx.x;
    int t = threadIdx.x;
    const float* src = XL + (size_t)b * DL;
    float s = 0.f;
    for (int k = t * 4; k < DL; k += 256 * 4) {
        float4 v = *(const float4*)(src + k);
        s += v.x * v.x + v.y * v.y + v.z * v.z + v.w * v.w;
    }
    __shared__ float red[256];
    red[t] = s;
    __syncthreads();
    for (int off = 128; off > 0; off >>= 1) {
        if (t < off) red[t] += red[t + off];
        __syncthreads();
    }
    if (t == 0) g_lsq[b] = red[0];
}

// ---------------- kernel 2: mma.sync Gram tile + fused dual mining ----------
// dot = Ahi*Bhi^T + Ahi*Blo^T + Alo*Bhi^T, fp32 accumulators in registers.
// 4 warps (2x2), warp tile 64x64, block tile 128x128, triangular grid.
__global__ __launch_bounds__(128, 2)
void gram_mma_kernel() {
    // triangular decode
    int kblk = blockIdx.x;
    int bx = (int)((sqrtf(8.0f * (float)kblk + 1.0f) - 1.0f) * 0.5f);
    while (bx * (bx + 1) / 2 > kblk) bx--;
    while ((bx + 1) * (bx + 2) / 2 <= kblk) bx++;
    int by = kblk - bx * (bx + 1) / 2;
    int rowBase = by * BM, colBase = bx * BN;
    bool diag = (bx == by);

    extern __shared__ char dyn[];
    __shared__ float sqR[BM], sqC[BN];
    __shared__ int   tgtR[BM], tgtC[BN];
    __shared__ float rPV[2][128], rNV[2][128];
    __shared__ int   rPI[2][128], rNI[2][128];
    __shared__ float cPV[2][128], cNV[2][128];
    __shared__ int   cPI[2][128], cNI[2][128];

    int t = threadIdx.x, wid = t >> 5, lid = t & 31;
    int wy = wid >> 1, wx = wid & 1;
    int warpRow = wy * 64, warpCol = wx * 64;
    unsigned sbase = smem_u32(dyn);

    sqR[t] = g_sq[rowBase + t]; tgtR[t] = g_tgt[rowBase + t];
    sqC[t] = g_sq[colBase + t]; tgtC[t] = g_tgt[colBase + t];
    __syncthreads();

    // gmem source bases for the 4 operand streams
    const __nv_bfloat16* gsrc[4] = {
        g_xhi + (size_t)rowBase * D, g_xlo + (size_t)rowBase * D,
        g_xhi + (size_t)colBase * D, g_xlo + (size_t)colBase * D
    };
    int r0 = t >> 1, h = t & 1;   // staging map: 2 threads per row, 16B each

    auto issueStage = [&](int j) {
        unsigned sb = sbase + (unsigned)((j & 1) * STAGE_B);
        size_t kb = (size_t)j * KS;
#pragma unroll
        for (int op = 0; op < 4; op++) {
#pragma unroll
            for (int ks = 0; ks < 2; ks++) {
#pragma unroll
                for (int rr = 0; rr < 2; rr++) {
                    int r = r0 + rr * 64;
                    unsigned dst = sb + (unsigned)((op * 2 + ks) * TILE_B) + tswz(r, h);
                    const void* src = gsrc[op] + (size_t)r * D + kb + ks * 16 + h * 8;
                    cp16(dst, src);
                }
            }
        }
    };

    float C[4][8][4];
#pragma unroll
    for (int mi = 0; mi < 4; mi++)
#pragma unroll
        for (int ni = 0; ni < 8; ni++)
#pragma unroll
            for (int q = 0; q < 4; q++) C[mi][ni][q] = 0.f;

    issueStage(0);
    asm volatile("cp.async.commit_group;" ::: "memory");

    int sub = lid >> 3, lr = lid & 7;

    for (int kt = 0; kt < NSTG; kt++) {
        if (kt + 1 < NSTG) {
            issueStage(kt + 1);
            asm volatile("cp.async.commit_group;" ::: "memory");
            asm volatile("cp.async.wait_group 1;" ::: "memory");
        } else {
            asm volatile("cp.async.wait_group 0;" ::: "memory");
        }
        __syncthreads();

        unsigned base = sbase + (unsigned)((kt & 1) * STAGE_B);
#pragma unroll
        for (int ks = 0; ks < 2; ks++) {
            unsigned aHiT = base + (unsigned)((0 * 2 + ks) * TILE_B);
            unsigned aLoT = base + (unsigned)((1 * 2 + ks) * TILE_B);
            unsigned bHiT = base + (unsigned)((2 * 2 + ks) * TILE_B);
            unsigned bLoT = base + (unsigned)((3 * 2 + ks) * TILE_B);

            // A fragments: 4 m-chunks, hi+lo
            unsigned ahi[4][4], alo[4][4];
#pragma unroll
            for (int mi = 0; mi < 4; mi++) {
                int r = warpRow + mi * 16 + (sub & 1) * 8 + lr;
                int hh = sub >> 1;
                unsigned off = tswz(r, hh);
                ldsm4(ahi[mi], aHiT + off);
                ldsm4(alo[mi], aLoT + off);
            }
            // B fragments: 4 n2-chunks (16 cols each), hi+lo; mma as we go
#pragma unroll
            for (int ni2 = 0; ni2 < 4; ni2++) {
                int rn = warpCol + ni2 * 16 + (sub >> 1) * 8 + lr;
                int hb = sub & 1;
                unsigned off = tswz(rn, hb);
                unsigned bh[4], bl[4];
                ldsm4(bh, bHiT + off);
                ldsm4(bl, bLoT + off);
#pragma unroll
                for (int f = 0; f < 2; f++) {
                    int ni = ni2 * 2 + f;
#pragma unroll
                    for (int mi = 0; mi < 4; mi++) {
                        mma16816(C[mi][ni], ahi[mi], bh[2 * f], bh[2 * f + 1]);
                        mma16816(C[mi][ni], ahi[mi], bl[2 * f], bl[2 * f + 1]);
                        mma16816(C[mi][ni], alo[mi], bh[2 * f], bh[2 * f + 1]);
                    }
                }
            }
        }
        __syncthreads();
    }

    // ---- epilogue: mine from register fragments ----
    // C[mi][ni][rh*2+cb]: row = warpRow + mi*16 + lid/4 + rh*8,
    //                     col = warpCol + ni*8 + (lid%4)*2 + cb
    // row direction -> slot bx
#pragma unroll
    for (int mi = 0; mi < 4; mi++) {
#pragma unroll
        for (int rh = 0; rh < 2; rh++) {
            int lrow = warpRow + mi * 16 + (lid >> 2) + rh * 8;
            float sq = sqR[lrow];
            int tr = tgtR[lrow];
            int gi = rowBase + lrow;
            float pv = -1e30f; int pi = 0x7fffffff;
            float nv =  1e30f; int ni_ = 0x7fffffff;
#pragma unroll
            for (int ni = 0; ni < 8; ni++) {
#pragma unroll
                for (int cb = 0; cb < 2; cb++) {
                    int lcol = warpCol + ni * 8 + (lid & 3) * 2 + cb;
                    float dot = C[mi][ni][rh * 2 + cb];
                    float dv = sqrtf(fmaxf(sq + sqC[lcol] - 2.f * dot, EPSC));
                    int gj = colBase + lcol;
                    if (tr == tgtC[lcol]) {
                        if (!(diag && lrow == lcol) && (dv > pv || (dv == pv && gj < pi))) { pv = dv; pi = gj; }
                    } else {
                        if (dv < nv || (dv == nv && gj < ni_)) { nv = dv; ni_ = gj; }
                    }
                }
            }
#pragma unroll
            for (int off = 1; off <= 2; off <<= 1) {
                float opv = __shfl_xor_sync(0xffffffffu, pv, off);
                int   opi = __shfl_xor_sync(0xffffffffu, pi, off);
                float onv = __shfl_xor_sync(0xffffffffu, nv, off);
                int   oni = __shfl_xor_sync(0xffffffffu, ni_, off);
                if (opv > pv || (opv == pv && opi < pi)) { pv = opv; pi = opi; }
                if (onv < nv || (onv == nv && oni < ni_)) { nv = onv; ni_ = oni; }
            }
            if ((lid & 3) == 0) {
                rPV[wx][lrow] = pv; rPI[wx][lrow] = pi;
                rNV[wx][lrow] = nv; rNI[wx][lrow] = ni_;
            }
        }
    }
    __syncthreads();
    {
        float pv = rPV[0][t]; int pi = rPI[0][t];
        float nv = rNV[0][t]; int ni_ = rNI[0][t];
        float v = rPV[1][t]; int id = rPI[1][t];
        if (v > pv || (v == pv && id < pi)) { pv = v; pi = id; }
        v = rNV[1][t]; id = rNI[1][t];
        if (v < nv || (v == nv && id < ni_)) { nv = v; ni_ = id; }
        g_posVal[bx * N + rowBase + t] = pv; g_posIdx[bx * N + rowBase + t] = pi;
        g_negVal[bx * N + rowBase + t] = nv; g_negIdx[bx * N + rowBase + t] = ni_;
    }

    // col direction (off-diagonal only) -> slot by
    if (!diag) {
        __syncthreads();
#pragma unroll
        for (int ni = 0; ni < 8; ni++) {
#pragma unroll
            for (int cb = 0; cb < 2; cb++) {
                int lcol = warpCol + ni * 8 + (lid & 3) * 2 + cb;
                float sqc = sqC[lcol];
                int tc = tgtC[lcol];
                float pv = -1e30f; int pi = 0x7fffffff;
                float nv =  1e30f; int ni_ = 0x7fffffff;
#pragma unroll
                for (int mi = 0; mi < 4; mi++) {
#pragma unroll
                    for (int rh = 0; rh < 2; rh++) {
                        int lrow = warpRow + mi * 16 + (lid >> 2) + rh * 8;
                        float dot = C[mi][ni][rh * 2 + cb];
                        float dv = sqrtf(fmaxf(sqR[lrow] + sqc - 2.f * dot, EPSC));
                        int gi = rowBase + lrow;
                        if (tc == tgtR[lrow]) {
                            if (dv > pv || (dv == pv && gi < pi)) { pv = dv; pi = gi; }
                        } else {
                            if (dv < nv || (dv == nv && gi < ni_)) { nv = dv; ni_ = gi; }
                        }
                    }
                }
#pragma unroll
                for (int off = 4; off <= 16; off <<= 1) {
                    float opv = __shfl_xor_sync(0xffffffffu, pv, off);
                    int   opi = __shfl_xor_sync(0xffffffffu, pi, off);
                    float onv = __shfl_xor_sync(0xffffffffu, nv, off);
                    int   oni = __shfl_xor_sync(0xffffffffu, ni_, off);
                    if (opv > pv || (opv == pv && opi < pi)) { pv = opv; pi = opi; }
                    if (onv < nv || (onv == nv && oni < ni_)) { nv = onv; ni_ = oni; }
                }
                if (lid < 4) {
                    cPV[wy][lcol] = pv; cPI[wy][lcol] = pi;
                    cNV[wy][lcol] = nv; cNI[wy][lcol] = ni_;
                }
            }
        }
        __syncthreads();
        {
            float pv = cPV[0][t]; int pi = cPI[0][t];
            float nv = cNV[0][t]; int ni_ = cNI[0][t];
            float v = cPV[1][t]; int id = cPI[1][t];
            if (v > pv || (v == pv && id < pi)) { pv = v; pi = id; }
            v = cNV[1][t]; id = cNI[1][t];
            if (v < nv || (v == nv && id < ni_)) { nv = v; ni_ = id; }
            g_posVal[by * N + colBase + t] = pv; g_posIdx[by * N + colBase + t] = pi;
            g_negVal[by * N + colBase + t] = nv; g_negIdx[by * N + colBase + t] = ni_;
        }
    }
}

// ---------------- kernel 3: combine partials + local distances --------------
__global__ void finalize_rows(const float* __restrict__ XL) {
    int warp = (blockIdx.x * blockDim.x + threadIdx.x) >> 5;
    int lane = threadIdx.x & 31;
    if (warp >= N) return;
    int row = warp;

    float pv = g_posVal[lane * N + row]; int pi = g_posIdx[lane * N + row];
    float nv = g_negVal[lane * N + row]; int ni = g_negIdx[lane * N + row];
    for (int off = 16; off > 0; off >>= 1) {
        float opv = __shfl_xor_sync(0xffffffffu, pv, off);
        int   opi = __shfl_xor_sync(0xffffffffu, pi, off);
        float onv = __shfl_xor_sync(0xffffffffu, nv, off);
        int   oni = __shfl_xor_sync(0xffffffffu, ni, off);
        if (opv > pv || (opv == pv && opi < pi)) { pv = opv; pi = opi; }
        if (onv < nv || (onv == nv && oni < ni)) { nv = onv; ni = oni; }
    }
    if (pi < 0 || pi >= N) pi = row;
    if (ni < 0 || ni >= N) ni = row;

    const float* li = XL + (size_t)row * DL;
    const float* lp = XL + (size_t)pi  * DL;
    const float* ln = XL + (size_t)ni  * DL;
    float dp = 0.f, dn = 0.f;
    for (int k = lane * 4; k < DL; k += 128) {
        float4 a = *(const float4*)(li + k);
        float4 b = *(const float4*)(lp + k);
        float4 c = *(const float4*)(ln + k);
        dp += a.x * b.x + a.y * b.y + a.z * b.z + a.w * b.w;
        dn += a.x * c.x + a.y * c.y + a.z * c.z + a.w * c.w;
    }
    for (int off = 16; off > 0; off >>= 1) {
        dp += __shfl_xor_sync(0xffffffffu, dp, off);
        dn += __shfl_xor_sync(0xffffffffu, dn, off);
    }
    if (lane == 0) {
        float lap = sqrtf(fmaxf(g_lsq[row] + g_lsq[pi] - 2.f * dp, EPSC));
        float lan = sqrtf(fmaxf(g_lsq[row] + g_lsq[ni] - 2.f * dn, EPSC));
        g_rowLoss[row]  = fmaxf(0.f, pv - nv + MARGIN);
        g_rowLocal[row] = fmaxf(0.f, lap - lan + MARGIN);
    }
}

// ---------------- kernel 4: deterministic means ----------------
__global__ void final_reduce(float* __restrict__ out, int out_size) {
    __shared__ float s1[256], s2[256];
    int t = threadIdx.x;
    float a = 0.f, b = 0.f;
    for (int i = t; i < N; i += 256) { a += g_rowLoss[i]; b += g_rowLocal[i]; }
    s1[t] = a; s2[t] = b;
    __syncthreads();
    for (int off = 128; off > 0; off >>= 1) {
        if (t < off) { s1[t] += s1[t + off]; s2[t] += s2[t + off]; }
        __syncthreads();
    }
    if (t == 0) {
        out[0] = s1[0] / (float)N;
        if (out_size > 1) out[1] = s2[0] / (float)N;
    }
}

// ---------------- launch ----------------
extern "C" void kernel_launch(void* const* d_in, const int* in_sizes, int n_in,
                              void* d_out, int out_size) {
    const float* X  = (const float*)d_in[0];
    const float* XL = (const float*)d_in[1];
    const int*   T  = (const int*)d_in[2];
    (void)in_sizes; (void)n_in;

    cudaFuncSetAttribute(gram_mma_kernel,
                         cudaFuncAttributeMaxDynamicSharedMemorySize, DYN_B);

    prep_targets<<<1, 1024>>>(T);
    convert_kernel<<<N, 256>>>(X);
    lnorms_kernel<<<N, 256>>>(XL);
    gram_mma_kernel<<<NBLK, 128, DYN_B>>>();
    finalize_rows<<<N / 8, 256>>>(XL);
    final_reduce<<<1, 256>>>((float*)d_out, out_size);
}

// round 10
// speedup vs baseline: 3.7240x; 1.0378x over previous
#include <cuda_runtime.h>
#include <cuda_bf16.h>
#include <cstdint>

#define N    4096
#define D    2048
#define DL   1024
#define BM   128
#define BN   128
#define KS   32                  // k elems per pipeline stage
#define NSTG (D / KS)            // 64
#define PIPE 3                   // cp.async stages
#define NTILE (N / BN)           // 32
#define NBLK  (NTILE * (NTILE + 1) / 2)  // 528
#define TILE_B   4096            // one 128x16 bf16 sub-tile
#define STAGE_B  (8 * TILE_B)    // {Ahi,Alo,Bhi,Blo} x {k0-15,k16-31} = 32 KB
#define DYN_B    (PIPE * STAGE_B)  // 96 KB
#define MARGIN 0.3f
#define EPSC   1e-12f

// ---------------- scratch (no allocations allowed) ----------------
__device__ int   g_tgt[N];
__device__ float g_sq[N];
__device__ float g_lsq[N];
__device__ __nv_bfloat16 g_xhi[(size_t)N * D];
__device__ __nv_bfloat16 g_xlo[(size_t)N * D];
__device__ float g_posVal[NTILE * N];
__device__ int   g_posIdx[NTILE * N];
__device__ float g_negVal[NTILE * N];
__device__ int   g_negIdx[NTILE * N];
__device__ float g_rowLoss[N];
__device__ float g_rowLocal[N];

// ---------------- helpers ----------------
__device__ __forceinline__ unsigned smem_u32(const void* p) {
    unsigned a;
    asm("{ .reg .u64 t; cvta.to.shared.u64 t, %1; cvt.u32.u64 %0, t; }" : "=r"(a) : "l"(p));
    return a;
}
__device__ __forceinline__ void cp16(unsigned dst, const void* src) {
    asm volatile("cp.async.cg.shared.global [%0], [%1], 16;" :: "r"(dst), "l"(src) : "memory");
}
__device__ __forceinline__ void ldsm4(unsigned* r, unsigned addr) {
    asm volatile("ldmatrix.sync.aligned.m8n8.x4.shared.b16 {%0,%1,%2,%3}, [%4];"
        : "=r"(r[0]), "=r"(r[1]), "=r"(r[2]), "=r"(r[3]) : "r"(addr));
}
__device__ __forceinline__ void mma16816(float* c, const unsigned* a, unsigned b0, unsigned b1) {
    asm volatile("mma.sync.aligned.m16n8k16.row.col.f32.bf16.bf16.f32 "
        "{%0,%1,%2,%3}, {%4,%5,%6,%7}, {%8,%9}, {%0,%1,%2,%3};"
        : "+f"(c[0]), "+f"(c[1]), "+f"(c[2]), "+f"(c[3])
        : "r"(a[0]), "r"(a[1]), "r"(a[2]), "r"(a[3]), "r"(b0), "r"(b1));
}
// swizzled offset within a 128x16 bf16 tile: row r (0..127), 16B half h (0..1)
__device__ __forceinline__ unsigned tswz(int r, int h) {
    return (unsigned)(r * 32 + ((h * 16) ^ ((r & 4) << 2)));
}

// ---------------- kernel 0: normalize targets (int32 vs int64 autodetect) ----
__global__ void prep_targets(const int* __restrict__ T32) {
    int f = 0;
    for (int i = threadIdx.x; i < N / 2; i += blockDim.x) f |= T32[2 * i + 1];
    int any = __syncthreads_or(f);
    bool is64 = (any == 0);
    for (int i = threadIdx.x; i < N; i += blockDim.x)
        g_tgt[i] = is64 ? T32[2 * i] : T32[i];
}

// ---------------- kernel 1: split X into bf16 hi/lo + row norms -------------
__global__ void convert_kernel(const float* __restrict__ X) {
    int row = blockIdx.x;
    int t = threadIdx.x;
    const float* src = X + (size_t)row * D;
    float s = 0.f;
    for (int k = t * 4; k < D; k += 256 * 4) {
        float4 v = *(const float4*)(src + k);
        s += v.x * v.x + v.y * v.y + v.z * v.z + v.w * v.w;
        float xs[4] = {v.x, v.y, v.z, v.w};
        unsigned hb[4], lb[4];
#pragma unroll
        for (int i = 0; i < 4; i++) {
            __nv_bfloat16 h = __float2bfloat16(xs[i]);
            __nv_bfloat16 l = __float2bfloat16(xs[i] - __bfloat162float(h));
            hb[i] = (unsigned)__bfloat16_as_ushort(h);
            lb[i] = (unsigned)__bfloat16_as_ushort(l);
        }
        *(uint2*)&g_xhi[(size_t)row * D + k] = make_uint2(hb[0] | (hb[1] << 16), hb[2] | (hb[3] << 16));
        *(uint2*)&g_xlo[(size_t)row * D + k] = make_uint2(lb[0] | (lb[1] << 16), lb[2] | (lb[3] << 16));
    }
    __shared__ float red[256];
    red[t] = s;
    __syncthreads();
    for (int off = 128; off > 0; off >>= 1) {
        if (t < off) red[t] += red[t + off];
        __syncthreads();
    }
    if (t == 0) g_sq[row] = red[0];
}

// ---------------- kernel 1b: local-feature row norms ------------------------
__global__ void lnorms_kernel(const float* __restrict__ XL) {
    int b = blockIdx.x;
    int t = threadIdx.x;
    const float* src = XL + (size_t)b * DL;
    float s = 0.f;
    for (int k = t * 4; k < DL; k += 256 * 4) {
        float4 v = *(const float4*)(src + k);
        s += v.x * v.x + v.y * v.y + v.z * v.z + v.w * v.w;
    }
    __shared__ float red[256];
    red[t] = s;
    __syncthreads();
    for (int off = 128; off > 0; off >>= 1) {
        if (t < off) red[t] += red[t + off];
        __syncthreads();
    }
    if (t == 0) g_lsq[b] = red[0];
}

// ---------------- kernel 2: mma.sync Gram tile + fused dual mining ----------
// dot = Ahi*Bhi^T + Ahi*Blo^T + Alo*Bhi^T, fp32 accumulators in registers.
// 4 warps (2x2), warp tile 64x64, block tile 128x128, triangular grid.
// 3-stage cp.async pipeline; fragment-first loads; product-major mma order.
__global__ __launch_bounds__(128, 2)
void gram_mma_kernel() {
    // triangular decode
    int kblk = blockIdx.x;
    int bx = (int)((sqrtf(8.0f * (float)kblk + 1.0f) - 1.0f) * 0.5f);
    while (bx * (bx + 1) / 2 > kblk) bx--;
    while ((bx + 1) * (bx + 2) / 2 <= kblk) bx++;
    int by = kblk - bx * (bx + 1) / 2;
    int rowBase = by * BM, colBase = bx * BN;
    bool diag = (bx == by);

    extern __shared__ char dyn[];
    __shared__ float sqR[BM], sqC[BN];
    __shared__ int   tgtR[BM], tgtC[BN];
    __shared__ float rPV[2][128], rNV[2][128];
    __shared__ int   rPI[2][128], rNI[2][128];
    __shared__ float cPV[2][128], cNV[2][128];
    __shared__ int   cPI[2][128], cNI[2][128];

    int t = threadIdx.x, wid = t >> 5, lid = t & 31;
    int wy = wid >> 1, wx = wid & 1;
    int warpRow = wy * 64, warpCol = wx * 64;
    unsigned sbase = smem_u32(dyn);

    sqR[t] = g_sq[rowBase + t]; tgtR[t] = g_tgt[rowBase + t];
    sqC[t] = g_sq[colBase + t]; tgtC[t] = g_tgt[colBase + t];
    __syncthreads();

    // gmem source bases for the 4 operand streams
    const __nv_bfloat16* gsrc[4] = {
        g_xhi + (size_t)rowBase * D, g_xlo + (size_t)rowBase * D,
        g_xhi + (size_t)colBase * D, g_xlo + (size_t)colBase * D
    };
    int r0 = t >> 1, h = t & 1;   // staging map: 2 threads per row, 16B each

    auto issueStage = [&](int j) {
        unsigned sb = sbase + (unsigned)((j % PIPE) * STAGE_B);
        size_t kb = (size_t)j * KS;
#pragma unroll
        for (int op = 0; op < 4; op++) {
#pragma unroll
            for (int ks = 0; ks < 2; ks++) {
#pragma unroll
                for (int rr = 0; rr < 2; rr++) {
                    int r = r0 + rr * 64;
                    unsigned dst = sb + (unsigned)((op * 2 + ks) * TILE_B) + tswz(r, h);
                    const void* src = gsrc[op] + (size_t)r * D + kb + ks * 16 + h * 8;
                    cp16(dst, src);
                }
            }
        }
        asm volatile("cp.async.commit_group;" ::: "memory");
    };

    float C[4][8][4];
#pragma unroll
    for (int mi = 0; mi < 4; mi++)
#pragma unroll
        for (int ni = 0; ni < 8; ni++)
#pragma unroll
            for (int q = 0; q < 4; q++) C[mi][ni][q] = 0.f;

    // hoisted ldsm offsets (constant per warp)
    int sub = lid >> 3, lr = lid & 7;
    unsigned offA[4], offB[4];
#pragma unroll
    for (int mi = 0; mi < 4; mi++)
        offA[mi] = tswz(warpRow + mi * 16 + (sub & 1) * 8 + lr, sub >> 1);
#pragma unroll
    for (int ni2 = 0; ni2 < 4; ni2++)
        offB[ni2] = tswz(warpCol + ni2 * 16 + (sub >> 1) * 8 + lr, sub & 1);

    issueStage(0);
    issueStage(1);

    for (int kt = 0; kt < NSTG; kt++) {
        if (kt + 1 < NSTG) {
            asm volatile("cp.async.wait_group 1;" ::: "memory");
        } else {
            asm volatile("cp.async.wait_group 0;" ::: "memory");
        }
        __syncthreads();
        if (kt + 2 < NSTG) issueStage(kt + 2);

        unsigned base = sbase + (unsigned)((kt % PIPE) * STAGE_B);
#pragma unroll
        for (int ks = 0; ks < 2; ks++) {
            unsigned aHiT = base + (unsigned)((0 * 2 + ks) * TILE_B);
            unsigned aLoT = base + (unsigned)((1 * 2 + ks) * TILE_B);
            unsigned bHiT = base + (unsigned)((2 * 2 + ks) * TILE_B);
            unsigned bLoT = base + (unsigned)((3 * 2 + ks) * TILE_B);

            // load ALL fragments for this k16 slice first (pipelined ldsm)
            unsigned ahi[4][4], alo[4][4], bh[4][4], bl[4][4];
#pragma unroll
            for (int mi = 0; mi < 4; mi++) ldsm4(ahi[mi], aHiT + offA[mi]);
#pragma unroll
            for (int ni2 = 0; ni2 < 4; ni2++) ldsm4(bh[ni2], bHiT + offB[ni2]);
#pragma unroll
            for (int mi = 0; mi < 4; mi++) ldsm4(alo[mi], aLoT + offA[mi]);
#pragma unroll
            for (int ni2 = 0; ni2 < 4; ni2++) ldsm4(bl[ni2], bLoT + offB[ni2]);

            // product-major: 3 passes of 32 independent mma (no accum chains)
#pragma unroll
            for (int mi = 0; mi < 4; mi++)
#pragma unroll
                for (int ni2 = 0; ni2 < 4; ni2++)
#pragma unroll
                    for (int f = 0; f < 2; f++)
                        mma16816(C[mi][ni2 * 2 + f], ahi[mi], bh[ni2][2 * f], bh[ni2][2 * f + 1]);
#pragma unroll
            for (int mi = 0; mi < 4; mi++)
#pragma unroll
                for (int ni2 = 0; ni2 < 4; ni2++)
#pragma unroll
                    for (int f = 0; f < 2; f++)
                        mma16816(C[mi][ni2 * 2 + f], ahi[mi], bl[ni2][2 * f], bl[ni2][2 * f + 1]);
#pragma unroll
            for (int mi = 0; mi < 4; mi++)
#pragma unroll
                for (int ni2 = 0; ni2 < 4; ni2++)
#pragma unroll
                    for (int f = 0; f < 2; f++)
                        mma16816(C[mi][ni2 * 2 + f], alo[mi], bh[ni2][2 * f], bh[ni2][2 * f + 1]);
        }
    }

    // ---- epilogue: mine from register fragments ----
    // C[mi][ni][rh*2+cb]: row = warpRow + mi*16 + lid/4 + rh*8,
    //                     col = warpCol + ni*8 + (lid%4)*2 + cb
    // row direction -> slot bx
#pragma unroll
    for (int mi = 0; mi < 4; mi++) {
#pragma unroll
        for (int rh = 0; rh < 2; rh++) {
            int lrow = warpRow + mi * 16 + (lid >> 2) + rh * 8;
            float sq = sqR[lrow];
            int tr = tgtR[lrow];
            int gi = rowBase + lrow;
            float pv = -1e30f; int pi = 0x7fffffff;
            float nv =  1e30f; int ni_ = 0x7fffffff;
#pragma unroll
            for (int ni = 0; ni < 8; ni++) {
#pragma unroll
                for (int cb = 0; cb < 2; cb++) {
                    int lcol = warpCol + ni * 8 + (lid & 3) * 2 + cb;
                    float dot = C[mi][ni][rh * 2 + cb];
                    float dv = sqrtf(fmaxf(sq + sqC[lcol] - 2.f * dot, EPSC));
                    int gj = colBase + lcol;
                    if (tr == tgtC[lcol]) {
                        if (!(diag && lrow == lcol) && (dv > pv || (dv == pv && gj < pi))) { pv = dv; pi = gj; }
                    } else {
                        if (dv < nv || (dv == nv && gj < ni_)) { nv = dv; ni_ = gj; }
                    }
                }
            }
#pragma unroll
            for (int off = 1; off <= 2; off <<= 1) {
                float opv = __shfl_xor_sync(0xffffffffu, pv, off);
                int   opi = __shfl_xor_sync(0xffffffffu, pi, off);
                float onv = __shfl_xor_sync(0xffffffffu, nv, off);
                int   oni = __shfl_xor_sync(0xffffffffu, ni_, off);
                if (opv > pv || (opv == pv && opi < pi)) { pv = opv; pi = opi; }
                if (onv < nv || (onv == nv && oni < ni_)) { nv = onv; ni_ = oni; }
            }
            if ((lid & 3) == 0) {
                rPV[wx][lrow] = pv; rPI[wx][lrow] = pi;
                rNV[wx][lrow] = nv; rNI[wx][lrow] = ni_;
            }
        }
    }
    __syncthreads();
    {
        float pv = rPV[0][t]; int pi = rPI[0][t];
        float nv = rNV[0][t]; int ni_ = rNI[0][t];
        float v = rPV[1][t]; int id = rPI[1][t];
        if (v > pv || (v == pv && id < pi)) { pv = v; pi = id; }
        v = rNV[1][t]; id = rNI[1][t];
        if (v < nv || (v == nv && id < ni_)) { nv = v; ni_ = id; }
        g_posVal[bx * N + rowBase + t] = pv; g_posIdx[bx * N + rowBase + t] = pi;
        g_negVal[bx * N + rowBase + t] = nv; g_negIdx[bx * N + rowBase + t] = ni_;
    }

    // col direction (off-diagonal only) -> slot by
    if (!diag) {
        __syncthreads();
#pragma unroll
        for (int ni = 0; ni < 8; ni++) {
#pragma unroll
            for (int cb = 0; cb < 2; cb++) {
                int lcol = warpCol + ni * 8 + (lid & 3) * 2 + cb;
                float sqc = sqC[lcol];
                int tc = tgtC[lcol];
                float pv = -1e30f; int pi = 0x7fffffff;
                float nv =  1e30f; int ni_ = 0x7fffffff;
#pragma unroll
                for (int mi = 0; mi < 4; mi++) {
#pragma unroll
                    for (int rh = 0; rh < 2; rh++) {
                        int lrow = warpRow + mi * 16 + (lid >> 2) + rh * 8;
                        float dot = C[mi][ni][rh * 2 + cb];
                        float dv = sqrtf(fmaxf(sqR[lrow] + sqc - 2.f * dot, EPSC));
                        int gi = rowBase + lrow;
                        if (tc == tgtR[lrow]) {
                            if (dv > pv || (dv == pv && gi < pi)) { pv = dv; pi = gi; }
                        } else {
                            if (dv < nv || (dv == nv && gi < ni_)) { nv = dv; ni_ = gi; }
                        }
                    }
                }
#pragma unroll
                for (int off = 4; off <= 16; off <<= 1) {
                    float opv = __shfl_xor_sync(0xffffffffu, pv, off);
                    int   opi = __shfl_xor_sync(0xffffffffu, pi, off);
                    float onv = __shfl_xor_sync(0xffffffffu, nv, off);
                    int   oni = __shfl_xor_sync(0xffffffffu, ni_, off);
                    if (opv > pv || (opv == pv && opi < pi)) { pv = opv; pi = opi; }
                    if (onv < nv || (onv == nv && oni < ni_)) { nv = onv; ni_ = oni; }
                }
                if (lid < 4) {
                    cPV[wy][lcol] = pv; cPI[wy][lcol] = pi;
                    cNV[wy][lcol] = nv; cNI[wy][lcol] = ni_;
                }
            }
        }
        __syncthreads();
        {
            float pv = cPV[0][t]; int pi = cPI[0][t];
            float nv = cNV[0][t]; int ni_ = cNI[0][t];
            float v = cPV[1][t]; int id = cPI[1][t];
            if (v > pv || (v == pv && id < pi)) { pv = v; pi = id; }
            v = cNV[1][t]; id = cNI[1][t];
            if (v < nv || (v == nv && id < ni_)) { nv = v; ni_ = id; }
            g_posVal[by * N + colBase + t] = pv; g_posIdx[by * N + colBase + t] = pi;
            g_negVal[by * N + colBase + t] = nv; g_negIdx[by * N + colBase + t] = ni_;
        }
    }
}

// ---------------- kernel 3: combine partials + local distances --------------
__global__ void finalize_rows(const float* __restrict__ XL) {
    int warp = (blockIdx.x * blockDim.x + threadIdx.x) >> 5;
    int lane = threadIdx.x & 31;
    if (warp >= N) return;
    int row = warp;

    float pv = g_posVal[lane * N + row]; int pi = g_posIdx[lane * N + row];
    float nv = g_negVal[lane * N + row]; int ni = g_negIdx[lane * N + row];
    for (int off = 16; off > 0; off >>= 1) {
        float opv = __shfl_xor_sync(0xffffffffu, pv, off);
        int   opi = __shfl_xor_sync(0xffffffffu, pi, off);
        float onv = __shfl_xor_sync(0xffffffffu, nv, off);
        int   oni = __shfl_xor_sync(0xffffffffu, ni, off);
        if (opv > pv || (opv == pv && opi < pi)) { pv = opv; pi = opi; }
        if (onv < nv || (onv == nv && oni < ni)) { nv = onv; ni = oni; }
    }
    if (pi < 0 || pi >= N) pi = row;
    if (ni < 0 || ni >= N) ni = row;

    const float* li = XL + (size_t)row * DL;
    const float* lp = XL + (size_t)pi  * DL;
    const float* ln = XL + (size_t)ni  * DL;
    float dp = 0.f, dn = 0.f;
    for (int k = lane * 4; k < DL; k += 128) {
        float4 a = *(const float4*)(li + k);
        float4 b = *(const float4*)(lp + k);
        float4 c = *(const float4*)(ln + k);
        dp += a.x * b.x + a.y * b.y + a.z * b.z + a.w * b.w;
        dn += a.x * c.x + a.y * c.y + a.z * c.z + a.w * c.w;
    }
    for (int off = 16; off > 0; off >>= 1) {
        dp += __shfl_xor_sync(0xffffffffu, dp, off);
        dn += __shfl_xor_sync(0xffffffffu, dn, off);
    }
    if (lane == 0) {
        float lap = sqrtf(fmaxf(g_lsq[row] + g_lsq[pi] - 2.f * dp, EPSC));
        float lan = sqrtf(fmaxf(g_lsq[row] + g_lsq[ni] - 2.f * dn, EPSC));
        g_rowLoss[row]  = fmaxf(0.f, pv - nv + MARGIN);
        g_rowLocal[row] = fmaxf(0.f, lap - lan + MARGIN);
    }
}

// ---------------- kernel 4: deterministic means ----------------
__global__ void final_reduce(float* __restrict__ out, int out_size) {
    __shared__ float s1[256], s2[256];
    int t = threadIdx.x;
    float a = 0.f, b = 0.f;
    for (int i = t; i < N; i += 256) { a += g_rowLoss[i]; b += g_rowLocal[i]; }
    s1[t] = a; s2[t] = b;
    __syncthreads();
    for (int off = 128; off > 0; off >>= 1) {
        if (t < off) { s1[t] += s1[t + off]; s2[t] += s2[t + off]; }
        __syncthreads();
    }
    if (t == 0) {
        out[0] = s1[0] / (float)N;
        if (out_size > 1) out[1] = s2[0] / (float)N;
    }
}

// ---------------- launch ----------------
extern "C" void kernel_launch(void* const* d_in, const int* in_sizes, int n_in,
                              void* d_out, int out_size) {
    const float* X  = (const float*)d_in[0];
    const float* XL = (const float*)d_in[1];
    const int*   T  = (const int*)d_in[2];
    (void)in_sizes; (void)n_in;

    cudaFuncSetAttribute(gram_mma_kernel,
                         cudaFuncAttributeMaxDynamicSharedMemorySize, DYN_B);

    prep_targets<<<1, 1024>>>(T);
    convert_kernel<<<N, 256>>>(X);
    lnorms_kernel<<<N, 256>>>(XL);
    gram_mma_kernel<<<NBLK, 128, DYN_B>>>();
    finalize_rows<<<N / 8, 256>>>(XL);
    final_reduce<<<1, 256>>>((float*)d_out, out_size);
}

// round 11
// speedup vs baseline: 4.0464x; 1.0866x over previous
#include <cuda_runtime.h>
#include <cuda_bf16.h>
#include <cstdint>

#define N    4096
#define D    2048
#define DL   1024
#define BM   128
#define BN   128
#define KS   32                  // k elems per pipeline stage
#define NSTG (D / KS)            // 64
#define PIPE 3                   // cp.async stages
#define NTILE (N / BN)           // 32
#define NBLK  (NTILE * (NTILE + 1) / 2)  // 528
#define TILE_B   4096            // one 128x16 bf16 sub-tile
#define STAGE_B  (8 * TILE_B)    // {Ahi,Alo,Bhi,Blo} x {k0-15,k16-31} = 32 KB
#define DYN_B    (PIPE * STAGE_B)  // 96 KB
#define MARGIN 0.3f
#define EPSC   1e-12f

// ---------------- scratch (no allocations allowed) ----------------
__device__ int   g_tgt[N];
__device__ float g_sq[N];
__device__ float g_lsq[N];
__device__ __nv_bfloat16 g_xhi[(size_t)N * D];
__device__ __nv_bfloat16 g_xlo[(size_t)N * D];
__device__ float g_posVal[NTILE * N];
__device__ int   g_posIdx[NTILE * N];
__device__ float g_negVal[NTILE * N];
__device__ int   g_negIdx[NTILE * N];
__device__ float g_rowLoss[N];
__device__ float g_rowLocal[N];

// ---------------- helpers ----------------
__device__ __forceinline__ unsigned smem_u32(const void* p) {
    unsigned a;
    asm("{ .reg .u64 t; cvta.to.shared.u64 t, %1; cvt.u32.u64 %0, t; }" : "=r"(a) : "l"(p));
    return a;
}
__device__ __forceinline__ void cp16(unsigned dst, const void* src) {
    asm volatile("cp.async.cg.shared.global [%0], [%1], 16;" :: "r"(dst), "l"(src) : "memory");
}
__device__ __forceinline__ void ldsm4(unsigned* r, unsigned addr) {
    asm volatile("ldmatrix.sync.aligned.m8n8.x4.shared.b16 {%0,%1,%2,%3}, [%4];"
        : "=r"(r[0]), "=r"(r[1]), "=r"(r[2]), "=r"(r[3]) : "r"(addr));
}
__device__ __forceinline__ void mma16816(float* c, const unsigned* a, unsigned b0, unsigned b1) {
    asm volatile("mma.sync.aligned.m16n8k16.row.col.f32.bf16.bf16.f32 "
        "{%0,%1,%2,%3}, {%4,%5,%6,%7}, {%8,%9}, {%0,%1,%2,%3};"
        : "+f"(c[0]), "+f"(c[1]), "+f"(c[2]), "+f"(c[3])
        : "r"(a[0]), "r"(a[1]), "r"(a[2]), "r"(a[3]), "r"(b0), "r"(b1));
}
// swizzled offset within a 128x16 bf16 tile: row r (0..127), 16B half h (0..1)
__device__ __forceinline__ unsigned tswz(int r, int h) {
    return (unsigned)(r * 32 + ((h * 16) ^ ((r & 4) << 2)));
}

// ---------------- kernel 0: normalize targets (int32 vs int64 autodetect) ----
__global__ void prep_targets(const int* __restrict__ T32) {
    int f = 0;
    for (int i = threadIdx.x; i < N / 2; i += blockDim.x) f |= T32[2 * i + 1];
    int any = __syncthreads_or(f);
    bool is64 = (any == 0);
    for (int i = threadIdx.x; i < N; i += blockDim.x)
        g_tgt[i] = is64 ? T32[2 * i] : T32[i];
}

// ---------------- kernel 1: split X into bf16 hi/lo + row norms -------------
__global__ void convert_kernel(const float* __restrict__ X) {
    int row = blockIdx.x;
    int t = threadIdx.x;
    const float* src = X + (size_t)row * D;
    float s = 0.f;
    for (int k = t * 4; k < D; k += 256 * 4) {
        float4 v = *(const float4*)(src + k);
        s += v.x * v.x + v.y * v.y + v.z * v.z + v.w * v.w;
        float xs[4] = {v.x, v.y, v.z, v.w};
        unsigned hb[4], lb[4];
#pragma unroll
        for (int i = 0; i < 4; i++) {
            __nv_bfloat16 h = __float2bfloat16(xs[i]);
            __nv_bfloat16 l = __float2bfloat16(xs[i] - __bfloat162float(h));
            hb[i] = (unsigned)__bfloat16_as_ushort(h);
            lb[i] = (unsigned)__bfloat16_as_ushort(l);
        }
        *(uint2*)&g_xhi[(size_t)row * D + k] = make_uint2(hb[0] | (hb[1] << 16), hb[2] | (hb[3] << 16));
        *(uint2*)&g_xlo[(size_t)row * D + k] = make_uint2(lb[0] | (lb[1] << 16), lb[2] | (lb[3] << 16));
    }
    __shared__ float red[256];
    red[t] = s;
    __syncthreads();
    for (int off = 128; off > 0; off >>= 1) {
        if (t < off) red[t] += red[t + off];
        __syncthreads();
    }
    if (t == 0) g_sq[row] = red[0];
}

// ---------------- kernel 1b: local-feature row norms ------------------------
__global__ void lnorms_kernel(const float* __restrict__ XL) {
    int b = blockIdx.x;
    int t = threadIdx.x;
    const float* src = XL + (size_t)b * DL;
    float s = 0.f;
    for (int k = t * 4; k < DL; k += 256 * 4) {
        float4 v = *(const float4*)(src + k);
        s += v.x * v.x + v.y * v.y + v.z * v.z + v.w * v.w;
    }
    __shared__ float red[256];
    red[t] = s;
    __syncthreads();
    for (int off = 128; off > 0; off >>= 1) {
        if (t < off) red[t] += red[t + off];
        __syncthreads();
    }
    if (t == 0) g_lsq[b] = red[0];
}

// ---------------- kernel 2: mma.sync Gram tile + fused dual mining ----------
// dot = Ahi*Bhi^T + Ahi*Blo^T + Alo*Bhi^T, fp32 accumulators in registers.
// 8 warps (2x4), warp tile 64x32, block tile 128x128, triangular grid.
// 16 warps/SM (4 per SMSP) to keep the tensor pipe covered.
__global__ __launch_bounds__(256, 2)
void gram_mma_kernel() {
    // triangular decode
    int kblk = blockIdx.x;
    int bx = (int)((sqrtf(8.0f * (float)kblk + 1.0f) - 1.0f) * 0.5f);
    while (bx * (bx + 1) / 2 > kblk) bx--;
    while ((bx + 1) * (bx + 2) / 2 <= kblk) bx++;
    int by = kblk - bx * (bx + 1) / 2;
    int rowBase = by * BM, colBase = bx * BN;
    bool diag = (bx == by);

    extern __shared__ char dyn[];
    __shared__ float sqR[BM], sqC[BN];
    __shared__ int   tgtR[BM], tgtC[BN];
    __shared__ float rPV[4][128], rNV[4][128];
    __shared__ int   rPI[4][128], rNI[4][128];
    __shared__ float cPV[2][128], cNV[2][128];
    __shared__ int   cPI[2][128], cNI[2][128];

    int t = threadIdx.x, wid = t >> 5, lid = t & 31;
    int wy = wid >> 2, wx = wid & 3;           // 2 x 4 warp grid
    int warpRow = wy * 64, warpCol = wx * 32;  // warp tile 64 x 32
    unsigned sbase = smem_u32(dyn);

    if (t < 128) {
        sqR[t] = g_sq[rowBase + t]; tgtR[t] = g_tgt[rowBase + t];
        sqC[t] = g_sq[colBase + t]; tgtC[t] = g_tgt[colBase + t];
    }
    __syncthreads();

    // gmem source bases for the 4 operand streams
    const __nv_bfloat16* gsrc[4] = {
        g_xhi + (size_t)rowBase * D, g_xlo + (size_t)rowBase * D,
        g_xhi + (size_t)colBase * D, g_xlo + (size_t)colBase * D
    };
    int r0 = t >> 1, h = t & 1;   // staging map: 2 threads per row, 16B each
    unsigned stoff = tswz(r0, h);

    auto issueStage = [&](int j) {
        unsigned sb = sbase + (unsigned)((j % PIPE) * STAGE_B);
        size_t kb = (size_t)j * KS;
#pragma unroll
        for (int op = 0; op < 4; op++) {
#pragma unroll
            for (int ks = 0; ks < 2; ks++) {
                unsigned dst = sb + (unsigned)((op * 2 + ks) * TILE_B) + stoff;
                const void* src = gsrc[op] + (size_t)r0 * D + kb + ks * 16 + h * 8;
                cp16(dst, src);
            }
        }
        asm volatile("cp.async.commit_group;" ::: "memory");
    };

    float C[4][4][4];   // [mi: 16-row chunk][ni: 8-col chunk][frag]
#pragma unroll
    for (int mi = 0; mi < 4; mi++)
#pragma unroll
        for (int ni = 0; ni < 4; ni++)
#pragma unroll
            for (int q = 0; q < 4; q++) C[mi][ni][q] = 0.f;

    // hoisted ldsm offsets (constant per warp)
    int sub = lid >> 3, lr = lid & 7;
    unsigned offA[4], offB[2];
#pragma unroll
    for (int mi = 0; mi < 4; mi++)
        offA[mi] = tswz(warpRow + mi * 16 + (sub & 1) * 8 + lr, sub >> 1);
#pragma unroll
    for (int ni2 = 0; ni2 < 2; ni2++)
        offB[ni2] = tswz(warpCol + ni2 * 16 + (sub >> 1) * 8 + lr, sub & 1);

    issueStage(0);
    issueStage(1);

    for (int kt = 0; kt < NSTG; kt++) {
        if (kt + 1 < NSTG) {
            asm volatile("cp.async.wait_group 1;" ::: "memory");
        } else {
            asm volatile("cp.async.wait_group 0;" ::: "memory");
        }
        __syncthreads();
        if (kt + 2 < NSTG) issueStage(kt + 2);

        unsigned base = sbase + (unsigned)((kt % PIPE) * STAGE_B);
#pragma unroll
        for (int ks = 0; ks < 2; ks++) {
            unsigned aHiT = base + (unsigned)((0 * 2 + ks) * TILE_B);
            unsigned aLoT = base + (unsigned)((1 * 2 + ks) * TILE_B);
            unsigned bHiT = base + (unsigned)((2 * 2 + ks) * TILE_B);
            unsigned bLoT = base + (unsigned)((3 * 2 + ks) * TILE_B);

            // phase-ordered fragments to limit live registers
            unsigned ahi[4][4], bh[2][4];
#pragma unroll
            for (int mi = 0; mi < 4; mi++) ldsm4(ahi[mi], aHiT + offA[mi]);
#pragma unroll
            for (int ni2 = 0; ni2 < 2; ni2++) ldsm4(bh[ni2], bHiT + offB[ni2]);
            // hh pass
#pragma unroll
            for (int mi = 0; mi < 4; mi++)
#pragma unroll
                for (int ni2 = 0; ni2 < 2; ni2++)
#pragma unroll
                    for (int f = 0; f < 2; f++)
                        mma16816(C[mi][ni2 * 2 + f], ahi[mi], bh[ni2][2 * f], bh[ni2][2 * f + 1]);
            // hl pass (bl transient)
            {
                unsigned bl[2][4];
#pragma unroll
                for (int ni2 = 0; ni2 < 2; ni2++) ldsm4(bl[ni2], bLoT + offB[ni2]);
#pragma unroll
                for (int mi = 0; mi < 4; mi++)
#pragma unroll
                    for (int ni2 = 0; ni2 < 2; ni2++)
#pragma unroll
                        for (int f = 0; f < 2; f++)
                            mma16816(C[mi][ni2 * 2 + f], ahi[mi], bl[ni2][2 * f], bl[ni2][2 * f + 1]);
            }
            // lh pass (alo transient)
            {
                unsigned alo[4][4];
#pragma unroll
                for (int mi = 0; mi < 4; mi++) ldsm4(alo[mi], aLoT + offA[mi]);
#pragma unroll
                for (int mi = 0; mi < 4; mi++)
#pragma unroll
                    for (int ni2 = 0; ni2 < 2; ni2++)
#pragma unroll
                        for (int f = 0; f < 2; f++)
                            mma16816(C[mi][ni2 * 2 + f], alo[mi], bh[ni2][2 * f], bh[ni2][2 * f + 1]);
            }
        }
    }

    // ---- epilogue: mine from register fragments ----
    // C[mi][ni][rh*2+cb]: row = warpRow + mi*16 + lid/4 + rh*8,
    //                     col = warpCol + ni*8 + (lid%4)*2 + cb
    // row direction -> slot bx
#pragma unroll
    for (int mi = 0; mi < 4; mi++) {
#pragma unroll
        for (int rh = 0; rh < 2; rh++) {
            int lrow = warpRow + mi * 16 + (lid >> 2) + rh * 8;
            float sq = sqR[lrow];
            int tr = tgtR[lrow];
            int gi = rowBase + lrow;
            float pv = -1e30f; int pi = 0x7fffffff;
            float nv =  1e30f; int ni_ = 0x7fffffff;
#pragma unroll
            for (int ni = 0; ni < 4; ni++) {
#pragma unroll
                for (int cb = 0; cb < 2; cb++) {
                    int lcol = warpCol + ni * 8 + (lid & 3) * 2 + cb;
                    float dot = C[mi][ni][rh * 2 + cb];
                    float dv = sqrtf(fmaxf(sq + sqC[lcol] - 2.f * dot, EPSC));
                    int gj = colBase + lcol;
                    if (tr == tgtC[lcol]) {
                        if (!(diag && lrow == lcol) && (dv > pv || (dv == pv && gj < pi))) { pv = dv; pi = gj; }
                    } else {
                        if (dv < nv || (dv == nv && gj < ni_)) { nv = dv; ni_ = gj; }
                    }
                }
            }
#pragma unroll
            for (int off = 1; off <= 2; off <<= 1) {
                float opv = __shfl_xor_sync(0xffffffffu, pv, off);
                int   opi = __shfl_xor_sync(0xffffffffu, pi, off);
                float onv = __shfl_xor_sync(0xffffffffu, nv, off);
                int   oni = __shfl_xor_sync(0xffffffffu, ni_, off);
                if (opv > pv || (opv == pv && opi < pi)) { pv = opv; pi = opi; }
                if (onv < nv || (onv == nv && oni < ni_)) { nv = onv; ni_ = oni; }
            }
            if ((lid & 3) == 0) {
                rPV[wx][lrow] = pv; rPI[wx][lrow] = pi;
                rNV[wx][lrow] = nv; rNI[wx][lrow] = ni_;
            }
        }
    }
    __syncthreads();
    if (t < 128) {
        float pv = rPV[0][t]; int pi = rPI[0][t];
        float nv = rNV[0][t]; int ni_ = rNI[0][t];
#pragma unroll
        for (int s = 1; s < 4; s++) {
            float v = rPV[s][t]; int id = rPI[s][t];
            if (v > pv || (v == pv && id < pi)) { pv = v; pi = id; }
            v = rNV[s][t]; id = rNI[s][t];
            if (v < nv || (v == nv && id < ni_)) { nv = v; ni_ = id; }
        }
        g_posVal[bx * N + rowBase + t] = pv; g_posIdx[bx * N + rowBase + t] = pi;
        g_negVal[bx * N + rowBase + t] = nv; g_negIdx[bx * N + rowBase + t] = ni_;
    }

    // col direction (off-diagonal only) -> slot by
    if (!diag) {
        __syncthreads();
#pragma unroll
        for (int ni = 0; ni < 4; ni++) {
#pragma unroll
            for (int cb = 0; cb < 2; cb++) {
                int lcol = warpCol + ni * 8 + (lid & 3) * 2 + cb;
                float sqc = sqC[lcol];
                int tc = tgtC[lcol];
                float pv = -1e30f; int pi = 0x7fffffff;
                float nv =  1e30f; int ni_ = 0x7fffffff;
#pragma unroll
                for (int mi = 0; mi < 4; mi++) {
#pragma unroll
                    for (int rh = 0; rh < 2; rh++) {
                        int lrow = warpRow + mi * 16 + (lid >> 2) + rh * 8;
                        float dot = C[mi][ni][rh * 2 + cb];
                        float dv = sqrtf(fmaxf(sqR[lrow] + sqc - 2.f * dot, EPSC));
                        int gi = rowBase + lrow;
                        if (tc == tgtR[lrow]) {
                            if (dv > pv || (dv == pv && gi < pi)) { pv = dv; pi = gi; }
                        } else {
                            if (dv < nv || (dv == nv && gi < ni_)) { nv = dv; ni_ = gi; }
                        }
                    }
                }
#pragma unroll
                for (int off = 4; off <= 16; off <<= 1) {
                    float opv = __shfl_xor_sync(0xffffffffu, pv, off);
                    int   opi = __shfl_xor_sync(0xffffffffu, pi, off);
                    float onv = __shfl_xor_sync(0xffffffffu, nv, off);
                    int   oni = __shfl_xor_sync(0xffffffffu, ni_, off);
                    if (opv > pv || (opv == pv && opi < pi)) { pv = opv; pi = opi; }
                    if (onv < nv || (onv == nv && oni < ni_)) { nv = onv; ni_ = oni; }
                }
                if (lid < 4) {
                    cPV[wy][lcol] = pv; cPI[wy][lcol] = pi;
                    cNV[wy][lcol] = nv; cNI[wy][lcol] = ni_;
                }
            }
        }
        __syncthreads();
        if (t < 128) {
            float pv = cPV[0][t]; int pi = cPI[0][t];
            float nv = cNV[0][t]; int ni_ = cNI[0][t];
            float v = cPV[1][t]; int id = cPI[1][t];
            if (v > pv || (v == pv && id < pi)) { pv = v; pi = id; }
            v = cNV[1][t]; id = cNI[1][t];
            if (v < nv || (v == nv && id < ni_)) { nv = v; ni_ = id; }
            g_posVal[by * N + colBase + t] = pv; g_posIdx[by * N + colBase + t] = pi;
            g_negVal[by * N + colBase + t] = nv; g_negIdx[by * N + colBase + t] = ni_;
        }
    }
}

// ---------------- kernel 3: combine partials + local distances --------------
__global__ void finalize_rows(const float* __restrict__ XL) {
    int warp = (blockIdx.x * blockDim.x + threadIdx.x) >> 5;
    int lane = threadIdx.x & 31;
    if (warp >= N) return;
    int row = warp;

    float pv = g_posVal[lane * N + row]; int pi = g_posIdx[lane * N + row];
    float nv = g_negVal[lane * N + row]; int ni = g_negIdx[lane * N + row];
    for (int off = 16; off > 0; off >>= 1) {
        float opv = __shfl_xor_sync(0xffffffffu, pv, off);
        int   opi = __shfl_xor_sync(0xffffffffu, pi, off);
        float onv = __shfl_xor_sync(0xffffffffu, nv, off);
        int   oni = __shfl_xor_sync(0xffffffffu, ni, off);
        if (opv > pv || (opv == pv && opi < pi)) { pv = opv; pi = opi; }
        if (onv < nv || (onv == nv && oni < ni)) { nv = onv; ni = oni; }
    }
    if (pi < 0 || pi >= N) pi = row;
    if (ni < 0 || ni >= N) ni = row;

    const float* li = XL + (size_t)row * DL;
    const float* lp = XL + (size_t)pi  * DL;
    const float* ln = XL + (size_t)ni  * DL;
    float dp = 0.f, dn = 0.f;
    for (int k = lane * 4; k < DL; k += 128) {
        float4 a = *(const float4*)(li + k);
        float4 b = *(const float4*)(lp + k);
        float4 c = *(const float4*)(ln + k);
        dp += a.x * b.x + a.y * b.y + a.z * b.z + a.w * b.w;
        dn += a.x * c.x + a.y * c.y + a.z * c.z + a.w * c.w;
    }
    for (int off = 16; off > 0; off >>= 1) {
        dp += __shfl_xor_sync(0xffffffffu, dp, off);
        dn += __shfl_xor_sync(0xffffffffu, dn, off);
    }
    if (lane == 0) {
        float lap = sqrtf(fmaxf(g_lsq[row] + g_lsq[pi] - 2.f * dp, EPSC));
        float lan = sqrtf(fmaxf(g_lsq[row] + g_lsq[ni] - 2.f * dn, EPSC));
        g_rowLoss[row]  = fmaxf(0.f, pv - nv + MARGIN);
        g_rowLocal[row] = fmaxf(0.f, lap - lan + MARGIN);
    }
}

// ---------------- kernel 4: deterministic means ----------------
__global__ void final_reduce(float* __restrict__ out, int out_size) {
    __shared__ float s1[256], s2[256];
    int t = threadIdx.x;
    float a = 0.f, b = 0.f;
    for (int i = t; i < N; i += 256) { a += g_rowLoss[i]; b += g_rowLocal[i]; }
    s1[t] = a; s2[t] = b;
    __syncthreads();
    for (int off = 128; off > 0; off >>= 1) {
        if (t < off) { s1[t] += s1[t + off]; s2[t] += s2[t + off]; }
        __syncthreads();
    }
    if (t == 0) {
        out[0] = s1[0] / (float)N;
        if (out_size > 1) out[1] = s2[0] / (float)N;
    }
}

// ---------------- launch ----------------
extern "C" void kernel_launch(void* const* d_in, const int* in_sizes, int n_in,
                              void* d_out, int out_size) {
    const float* X  = (const float*)d_in[0];
    const float* XL = (const float*)d_in[1];
    const int*   T  = (const int*)d_in[2];
    (void)in_sizes; (void)n_in;

    cudaFuncSetAttribute(gram_mma_kernel,
                         cudaFuncAttributeMaxDynamicSharedMemorySize, DYN_B);

    prep_targets<<<1, 1024>>>(T);
    convert_kernel<<<N, 256>>>(X);
    lnorms_kernel<<<N, 256>>>(XL);
    gram_mma_kernel<<<NBLK, 256, DYN_B>>>();
    finalize_rows<<<N / 8, 256>>>(XL);
    final_reduce<<<1, 256>>>((float*)d_out, out_size);
}

// round 12
// speedup vs baseline: 4.4669x; 1.1039x over previous
#include <cuda_runtime.h>
#include <cuda_bf16.h>
#include <cstdint>

#define N    4096
#define D    2048
#define DL   1024
#define BM   128
#define BN   128
#define KS   32                  // k elems per pipeline stage
#define NSTG (D / KS)            // 64
#define PIPE 4                   // cp.async stages
#define NTILE (N / BN)           // 32
#define NBLK  (NTILE * (NTILE + 1) / 2)  // 528
#define TILE_B   4096            // one 128x16 bf16 sub-tile
#define STAGE_B  (4 * TILE_B)    // {Ahi,Bhi} x {k0-15,k16-31} = 16 KB
#define DYN_B    (PIPE * STAGE_B)  // 64 KB
#define MARGIN 0.3f
#define EPSC   1e-12f
#define IINF   0x7fffffff

// ---------------- scratch (no allocations allowed) ----------------
__device__ int   g_tgt[N];
__device__ float g_sq[N];
__device__ float g_lsq[N];
__device__ __nv_bfloat16 g_xhi[(size_t)N * D];
__device__ float g_posVal[NTILE * 2 * N];
__device__ int   g_posIdx[NTILE * 2 * N];
__device__ float g_negVal[NTILE * 2 * N];
__device__ int   g_negIdx[NTILE * 2 * N];
__device__ float g_rowLoss[N];
__device__ float g_rowLocal[N];

// ---------------- helpers ----------------
__device__ __forceinline__ unsigned smem_u32(const void* p) {
    unsigned a;
    asm("{ .reg .u64 t; cvta.to.shared.u64 t, %1; cvt.u32.u64 %0, t; }" : "=r"(a) : "l"(p));
    return a;
}
__device__ __forceinline__ void cp16(unsigned dst, const void* src) {
    asm volatile("cp.async.cg.shared.global [%0], [%1], 16;" :: "r"(dst), "l"(src) : "memory");
}
__device__ __forceinline__ void ldsm4(unsigned* r, unsigned addr) {
    asm volatile("ldmatrix.sync.aligned.m8n8.x4.shared.b16 {%0,%1,%2,%3}, [%4];"
        : "=r"(r[0]), "=r"(r[1]), "=r"(r[2]), "=r"(r[3]) : "r"(addr));
}
__device__ __forceinline__ void mma16816(float* c, const unsigned* a, unsigned b0, unsigned b1) {
    asm volatile("mma.sync.aligned.m16n8k16.row.col.f32.bf16.bf16.f32 "
        "{%0,%1,%2,%3}, {%4,%5,%6,%7}, {%8,%9}, {%0,%1,%2,%3};"
        : "+f"(c[0]), "+f"(c[1]), "+f"(c[2]), "+f"(c[3])
        : "r"(a[0]), "r"(a[1]), "r"(a[2]), "r"(a[3]), "r"(b0), "r"(b1));
}
__device__ __forceinline__ unsigned tswz(int r, int h) {
    return (unsigned)(r * 32 + ((h * 16) ^ ((r & 4) << 2)));
}
// top-2 insert, "smaller is better", tie-break lower index
__device__ __forceinline__ void ins_min(float& v1, int& i1, float& v2, int& i2, float u, int j) {
    if (u < v1 || (u == v1 && j < i1)) { v2 = v1; i2 = i1; v1 = u; i1 = j; }
    else if (u < v2 || (u == v2 && j < i2)) { v2 = u; i2 = j; }
}
// top-2 insert, "larger is better", tie-break lower index
__device__ __forceinline__ void ins_max(float& v1, int& i1, float& v2, int& i2, float u, int j) {
    if (u > v1 || (u == v1 && j < i1)) { v2 = v1; i2 = i1; v1 = u; i1 = j; }
    else if (u > v2 || (u == v2 && j < i2)) { v2 = u; i2 = j; }
}
// butterfly merge of top-2 sets across lanes (disjoint underlying sets)
#define SHFL_MERGE2(INS, v1, i1, v2, i2, off) do { \
    float _ov1 = __shfl_xor_sync(0xffffffffu, v1, off); \
    int   _oi1 = __shfl_xor_sync(0xffffffffu, i1, off); \
    float _ov2 = __shfl_xor_sync(0xffffffffu, v2, off); \
    int   _oi2 = __shfl_xor_sync(0xffffffffu, i2, off); \
    INS(v1, i1, v2, i2, _ov1, _oi1); \
    INS(v1, i1, v2, i2, _ov2, _oi2); \
} while (0)

// ---------------- kernel 0: normalize targets (int32 vs int64 autodetect) ----
__global__ void prep_targets(const int* __restrict__ T32) {
    int f = 0;
    for (int i = threadIdx.x; i < N / 2; i += blockDim.x) f |= T32[2 * i + 1];
    int any = __syncthreads_or(f);
    bool is64 = (any == 0);
    for (int i = threadIdx.x; i < N; i += blockDim.x)
        g_tgt[i] = is64 ? T32[2 * i] : T32[i];
}

// ---------------- kernel 1: bf16 hi of X + row norms ------------------------
__global__ void convert_kernel(const float* __restrict__ X) {
    int row = blockIdx.x;
    int t = threadIdx.x;
    const float* src = X + (size_t)row * D;
    float s = 0.f;
    for (int k = t * 4; k < D; k += 256 * 4) {
        float4 v = *(const float4*)(src + k);
        s += v.x * v.x + v.y * v.y + v.z * v.z + v.w * v.w;
        unsigned h0 = (unsigned)__bfloat16_as_ushort(__float2bfloat16(v.x));
        unsigned h1 = (unsigned)__bfloat16_as_ushort(__float2bfloat16(v.y));
        unsigned h2 = (unsigned)__bfloat16_as_ushort(__float2bfloat16(v.z));
        unsigned h3 = (unsigned)__bfloat16_as_ushort(__float2bfloat16(v.w));
        *(uint2*)&g_xhi[(size_t)row * D + k] = make_uint2(h0 | (h1 << 16), h2 | (h3 << 16));
    }
    __shared__ float red[256];
    red[t] = s;
    __syncthreads();
    for (int off = 128; off > 0; off >>= 1) {
        if (t < off) red[t] += red[t + off];
        __syncthreads();
    }
    if (t == 0) g_sq[row] = red[0];
}

// ---------------- kernel 1b: local-feature row norms ------------------------
__global__ void lnorms_kernel(const float* __restrict__ XL) {
    int b = blockIdx.x;
    int t = threadIdx.x;
    const float* src = XL + (size_t)b * DL;
    float s = 0.f;
    for (int k = t * 4; k < DL; k += 256 * 4) {
        float4 v = *(const float4*)(src + k);
        s += v.x * v.x + v.y * v.y + v.z * v.z + v.w * v.w;
    }
    __shared__ float red[256];
    red[t] = s;
    __syncthreads();
    for (int off = 128; off > 0; off >>= 1) {
        if (t < off) red[t] += red[t + off];
        __syncthreads();
    }
    if (t == 0) g_lsq[b] = red[0];
}

// ---------------- kernel 2: 1-GEMM approx Gram + top-2 dual mining ----------
// dot_approx = Ahi*Bhi^T only. Mining keeps top-2 per (row, tile) per
// direction; exact refinement happens in finalize_rows.
__global__ __launch_bounds__(256, 2)
void gram_mma_kernel() {
    int kblk = blockIdx.x;
    int bx = (int)((sqrtf(8.0f * (float)kblk + 1.0f) - 1.0f) * 0.5f);
    while (bx * (bx + 1) / 2 > kblk) bx--;
    while ((bx + 1) * (bx + 2) / 2 <= kblk) bx++;
    int by = kblk - bx * (bx + 1) / 2;
    int rowBase = by * BM, colBase = bx * BN;
    bool diag = (bx == by);

    extern __shared__ char dyn[];
    __shared__ float sqR[BM], sqC[BN];
    __shared__ int   tgtR[BM], tgtC[BN];
    __shared__ float rPV[4][2][128], rNV[4][2][128];
    __shared__ int   rPI[4][2][128], rNI[4][2][128];
    __shared__ float cPV[2][2][128], cNV[2][2][128];
    __shared__ int   cPI[2][2][128], cNI[2][2][128];

    int t = threadIdx.x, wid = t >> 5, lid = t & 31;
    int wy = wid >> 2, wx = wid & 3;           // 2 x 4 warp grid
    int warpRow = wy * 64, warpCol = wx * 32;  // warp tile 64 x 32
    unsigned sbase = smem_u32(dyn);

    if (t < 128) {
        sqR[t] = g_sq[rowBase + t]; tgtR[t] = g_tgt[rowBase + t];
        sqC[t] = g_sq[colBase + t]; tgtC[t] = g_tgt[colBase + t];
    }
    __syncthreads();

    const __nv_bfloat16* gsrc[2] = {
        g_xhi + (size_t)rowBase * D, g_xhi + (size_t)colBase * D
    };
    int r0 = t >> 1, h = t & 1;
    unsigned stoff = tswz(r0, h);

    auto issueStage = [&](int j) {
        unsigned sb = sbase + (unsigned)((j % PIPE) * STAGE_B);
        size_t kb = (size_t)j * KS;
#pragma unroll
        for (int op = 0; op < 2; op++) {
#pragma unroll
            for (int ks = 0; ks < 2; ks++) {
                unsigned dst = sb + (unsigned)((op * 2 + ks) * TILE_B) + stoff;
                const void* src = gsrc[op] + (size_t)r0 * D + kb + ks * 16 + h * 8;
                cp16(dst, src);
            }
        }
        asm volatile("cp.async.commit_group;" ::: "memory");
    };

    float C[4][4][4];
#pragma unroll
    for (int mi = 0; mi < 4; mi++)
#pragma unroll
        for (int ni = 0; ni < 4; ni++)
#pragma unroll
            for (int q = 0; q < 4; q++) C[mi][ni][q] = 0.f;

    int sub = lid >> 3, lr = lid & 7;
    unsigned offA[4], offB[2];
#pragma unroll
    for (int mi = 0; mi < 4; mi++)
        offA[mi] = tswz(warpRow + mi * 16 + (sub & 1) * 8 + lr, sub >> 1);
#pragma unroll
    for (int ni2 = 0; ni2 < 2; ni2++)
        offB[ni2] = tswz(warpCol + ni2 * 16 + (sub >> 1) * 8 + lr, sub & 1);

    issueStage(0);
    issueStage(1);
    issueStage(2);

    for (int kt = 0; kt < NSTG; kt++) {
        if (kt < NSTG - 2) {
            asm volatile("cp.async.wait_group 2;" ::: "memory");
        } else if (kt == NSTG - 2) {
            asm volatile("cp.async.wait_group 1;" ::: "memory");
        } else {
            asm volatile("cp.async.wait_group 0;" ::: "memory");
        }
        __syncthreads();
        if (kt + 3 < NSTG) issueStage(kt + 3);

        unsigned base = sbase + (unsigned)((kt % PIPE) * STAGE_B);
#pragma unroll
        for (int ks = 0; ks < 2; ks++) {
            unsigned aT = base + (unsigned)((0 * 2 + ks) * TILE_B);
            unsigned bT = base + (unsigned)((1 * 2 + ks) * TILE_B);
            unsigned ahi[4][4], bh[2][4];
#pragma unroll
            for (int mi = 0; mi < 4; mi++) ldsm4(ahi[mi], aT + offA[mi]);
#pragma unroll
            for (int ni2 = 0; ni2 < 2; ni2++) ldsm4(bh[ni2], bT + offB[ni2]);
#pragma unroll
            for (int mi = 0; mi < 4; mi++)
#pragma unroll
                for (int ni2 = 0; ni2 < 2; ni2++)
#pragma unroll
                    for (int f = 0; f < 2; f++)
                        mma16816(C[mi][ni2 * 2 + f], ahi[mi], bh[ni2][2 * f], bh[ni2][2 * f + 1]);
        }
    }

    // ---- epilogue: top-2 mining from register fragments ----
    // C[mi][ni][rh*2+cb]: row = warpRow + mi*16 + lid/4 + rh*8,
    //                     col = warpCol + ni*8 + (lid%4)*2 + cb
    // row direction -> slots (bx*2 + e)
#pragma unroll
    for (int mi = 0; mi < 4; mi++) {
#pragma unroll
        for (int rh = 0; rh < 2; rh++) {
            int lrow = warpRow + mi * 16 + (lid >> 2) + rh * 8;
            float sq = sqR[lrow];
            int tr = tgtR[lrow];
            float pv1 = -1e30f, pv2 = -1e30f; int pi1 = IINF, pi2 = IINF;
            float nv1 =  1e30f, nv2 =  1e30f; int ni1 = IINF, ni2 = IINF;
#pragma unroll
            for (int ni = 0; ni < 4; ni++) {
#pragma unroll
                for (int cb = 0; cb < 2; cb++) {
                    int lcol = warpCol + ni * 8 + (lid & 3) * 2 + cb;
                    float dot = C[mi][ni][rh * 2 + cb];
                    float dv = sqrtf(fmaxf(sq + sqC[lcol] - 2.f * dot, EPSC));
                    int gj = colBase + lcol;
                    if (tr == tgtC[lcol]) {
                        if (!(diag && lrow == lcol)) ins_max(pv1, pi1, pv2, pi2, dv, gj);
                    } else {
                        ins_min(nv1, ni1, nv2, ni2, dv, gj);
                    }
                }
            }
            SHFL_MERGE2(ins_max, pv1, pi1, pv2, pi2, 1);
            SHFL_MERGE2(ins_max, pv1, pi1, pv2, pi2, 2);
            SHFL_MERGE2(ins_min, nv1, ni1, nv2, ni2, 1);
            SHFL_MERGE2(ins_min, nv1, ni1, nv2, ni2, 2);
            if ((lid & 3) == 0) {
                rPV[wx][0][lrow] = pv1; rPI[wx][0][lrow] = pi1;
                rPV[wx][1][lrow] = pv2; rPI[wx][1][lrow] = pi2;
                rNV[wx][0][lrow] = nv1; rNI[wx][0][lrow] = ni1;
                rNV[wx][1][lrow] = nv2; rNI[wx][1][lrow] = ni2;
            }
        }
    }
    __syncthreads();
    if (t < 128) {
        float pv1 = -1e30f, pv2 = -1e30f; int pi1 = IINF, pi2 = IINF;
        float nv1 =  1e30f, nv2 =  1e30f; int ni1 = IINF, ni2 = IINF;
#pragma unroll
        for (int s = 0; s < 4; s++)
#pragma unroll
            for (int e = 0; e < 2; e++) {
                ins_max(pv1, pi1, pv2, pi2, rPV[s][e][t], rPI[s][e][t]);
                ins_min(nv1, ni1, nv2, ni2, rNV[s][e][t], rNI[s][e][t]);
            }
        int r = rowBase + t;
        g_posVal[(bx * 2 + 0) * N + r] = pv1; g_posIdx[(bx * 2 + 0) * N + r] = pi1;
        g_posVal[(bx * 2 + 1) * N + r] = pv2; g_posIdx[(bx * 2 + 1) * N + r] = pi2;
        g_negVal[(bx * 2 + 0) * N + r] = nv1; g_negIdx[(bx * 2 + 0) * N + r] = ni1;
        g_negVal[(bx * 2 + 1) * N + r] = nv2; g_negIdx[(bx * 2 + 1) * N + r] = ni2;
    }

    // col direction (off-diagonal only) -> slots (by*2 + e)
    if (!diag) {
        __syncthreads();
#pragma unroll
        for (int ni = 0; ni < 4; ni++) {
#pragma unroll
            for (int cb = 0; cb < 2; cb++) {
                int lcol = warpCol + ni * 8 + (lid & 3) * 2 + cb;
                float sqc = sqC[lcol];
                int tc = tgtC[lcol];
                float pv1 = -1e30f, pv2 = -1e30f; int pi1 = IINF, pi2 = IINF;
                float nv1 =  1e30f, nv2 =  1e30f; int ni1 = IINF, ni2 = IINF;
#pragma unroll
                for (int mi = 0; mi < 4; mi++) {
#pragma unroll
                    for (int rh = 0; rh < 2; rh++) {
                        int lrow = warpRow + mi * 16 + (lid >> 2) + rh * 8;
                        float dot = C[mi][ni][rh * 2 + cb];
                        float dv = sqrtf(fmaxf(sqR[lrow] + sqc - 2.f * dot, EPSC));
                        int gi = rowBase + lrow;
                        if (tc == tgtR[lrow]) ins_max(pv1, pi1, pv2, pi2, dv, gi);
                        else                  ins_min(nv1, ni1, nv2, ni2, dv, gi);
                    }
                }
                SHFL_MERGE2(ins_max, pv1, pi1, pv2, pi2, 4);
                SHFL_MERGE2(ins_max, pv1, pi1, pv2, pi2, 8);
                SHFL_MERGE2(ins_max, pv1, pi1, pv2, pi2, 16);
                SHFL_MERGE2(ins_min, nv1, ni1, nv2, ni2, 4);
                SHFL_MERGE2(ins_min, nv1, ni1, nv2, ni2, 8);
                SHFL_MERGE2(ins_min, nv1, ni1, nv2, ni2, 16);
                if (lid < 4) {
                    cPV[wy][0][lcol] = pv1; cPI[wy][0][lcol] = pi1;
                    cPV[wy][1][lcol] = pv2; cPI[wy][1][lcol] = pi2;
                    cNV[wy][0][lcol] = nv1; cNI[wy][0][lcol] = ni1;
                    cNV[wy][1][lcol] = nv2; cNI[wy][1][lcol] = ni2;
                }
            }
        }
        __syncthreads();
        if (t < 128) {
            float pv1 = -1e30f, pv2 = -1e30f; int pi1 = IINF, pi2 = IINF;
            float nv1 =  1e30f, nv2 =  1e30f; int ni1 = IINF, ni2 = IINF;
#pragma unroll
            for (int s = 0; s < 2; s++)
#pragma unroll
                for (int e = 0; e < 2; e++) {
                    ins_max(pv1, pi1, pv2, pi2, cPV[s][e][t], cPI[s][e][t]);
                    ins_min(nv1, ni1, nv2, ni2, cNV[s][e][t], cNI[s][e][t]);
                }
            int r = colBase + t;
            g_posVal[(by * 2 + 0) * N + r] = pv1; g_posIdx[(by * 2 + 0) * N + r] = pi1;
            g_posVal[(by * 2 + 1) * N + r] = pv2; g_posIdx[(by * 2 + 1) * N + r] = pi2;
            g_negVal[(by * 2 + 0) * N + r] = nv1; g_negIdx[(by * 2 + 0) * N + r] = ni1;
            g_negVal[(by * 2 + 1) * N + r] = nv2; g_negIdx[(by * 2 + 1) * N + r] = ni2;
        }
    }
}

// ---------------- kernel 3: top-4 select + exact fp32 refine + local --------
__device__ __forceinline__ float warpDot(const float* a, const float* b, int lane) {
    float s = 0.f;
    for (int k = lane * 4; k < D; k += 128) {
        float4 x = *(const float4*)(a + k);
        float4 y = *(const float4*)(b + k);
        s += x.x * y.x + x.y * y.y + x.z * y.z + x.w * y.w;
    }
#pragma unroll
    for (int off = 16; off > 0; off >>= 1)
        s += __shfl_xor_sync(0xffffffffu, s, off);
    return s;
}

__global__ void finalize_rows(const float* __restrict__ X, const float* __restrict__ XL) {
    int warp = (blockIdx.x * blockDim.x + threadIdx.x) >> 5;
    int lane = threadIdx.x & 31;
    if (warp >= N) return;
    int row = warp;

    // lane <-> tile slot; 2 entries each, per direction
    float pv[2], nvv[2]; int pidx[2], nidx[2];
#pragma unroll
    for (int e = 0; e < 2; e++) {
        pv[e]   = g_posVal[(lane * 2 + e) * N + row];
        pidx[e] = g_posIdx[(lane * 2 + e) * N + row];
        nvv[e]  = g_negVal[(lane * 2 + e) * N + row];
        nidx[e] = g_negIdx[(lane * 2 + e) * N + row];
    }

    // top-4 approx NEG (min) by iterative extraction
    int nsel[4];
#pragma unroll
    for (int it = 0; it < 4; it++) {
        float bv = 1e30f; int bi = IINF;
#pragma unroll
        for (int e = 0; e < 2; e++)
            if (nvv[e] < bv || (nvv[e] == bv && nidx[e] < bi)) { bv = nvv[e]; bi = nidx[e]; }
#pragma unroll
        for (int off = 16; off > 0; off >>= 1) {
            float ov = __shfl_xor_sync(0xffffffffu, bv, off);
            int   oi = __shfl_xor_sync(0xffffffffu, bi, off);
            if (ov < bv || (ov == bv && oi < bi)) { bv = ov; bi = oi; }
        }
        nsel[it] = bi;
#pragma unroll
        for (int e = 0; e < 2; e++)
            if (nidx[e] == bi) { nvv[e] = 1e30f; nidx[e] = IINF; }
    }
    // top-4 approx POS (max)
    int psel[4];
#pragma unroll
    for (int it = 0; it < 4; it++) {
        float bv = -1e30f; int bi = IINF;
#pragma unroll
        for (int e = 0; e < 2; e++)
            if (pv[e] > bv || (pv[e] == bv && pidx[e] < bi)) { bv = pv[e]; bi = pidx[e]; }
#pragma unroll
        for (int off = 16; off > 0; off >>= 1) {
            float ov = __shfl_xor_sync(0xffffffffu, bv, off);
            int   oi = __shfl_xor_sync(0xffffffffu, bi, off);
            if (ov > bv || (ov == bv && oi < bi)) { bv = ov; bi = oi; }
        }
        psel[it] = bi;
#pragma unroll
        for (int e = 0; e < 2; e++)
            if (pidx[e] == bi) { pv[e] = -1e30f; pidx[e] = IINF; }
    }

    // exact fp32 refinement of candidates
    const float* xr = X + (size_t)row * D;
    float sqr = g_sq[row];
    float bestPd = -1e30f; int bestPi = IINF;
#pragma unroll
    for (int it = 0; it < 4; it++) {
        int j = psel[it];
        if (j < 0 || j >= N) continue;
        float dot = warpDot(xr, X + (size_t)j * D, lane);
        float d = sqrtf(fmaxf(sqr + g_sq[j] - 2.f * dot, EPSC));
        if (d > bestPd || (d == bestPd && j < bestPi)) { bestPd = d; bestPi = j; }
    }
    float bestNd = 1e30f; int bestNi = IINF;
#pragma unroll
    for (int it = 0; it < 4; it++) {
        int j = nsel[it];
        if (j < 0 || j >= N) continue;
        float dot = warpDot(xr, X + (size_t)j * D, lane);
        float d = sqrtf(fmaxf(sqr + g_sq[j] - 2.f * dot, EPSC));
        if (d < bestNd || (d == bestNd && j < bestNi)) { bestNd = d; bestNi = j; }
    }
    int pi = (bestPi < 0 || bestPi >= N) ? row : bestPi;
    int ni = (bestNi < 0 || bestNi >= N) ? row : bestNi;

    // local feature distances
    const float* li = XL + (size_t)row * DL;
    const float* lp = XL + (size_t)pi  * DL;
    const float* ln = XL + (size_t)ni  * DL;
    float dp = 0.f, dn = 0.f;
    for (int k = lane * 4; k < DL; k += 128) {
        float4 a = *(const float4*)(li + k);
        float4 b = *(const float4*)(lp + k);
        float4 c = *(const float4*)(ln + k);
        dp += a.x * b.x + a.y * b.y + a.z * b.z + a.w * b.w;
        dn += a.x * c.x + a.y * c.y + a.z * c.z + a.w * c.w;
    }
#pragma unroll
    for (int off = 16; off > 0; off >>= 1) {
        dp += __shfl_xor_sync(0xffffffffu, dp, off);
        dn += __shfl_xor_sync(0xffffffffu, dn, off);
    }
    if (lane == 0) {
        float lap = sqrtf(fmaxf(g_lsq[row] + g_lsq[pi] - 2.f * dp, EPSC));
        float lan = sqrtf(fmaxf(g_lsq[row] + g_lsq[ni] - 2.f * dn, EPSC));
        g_rowLoss[row]  = fmaxf(0.f, bestPd - bestNd + MARGIN);
        g_rowLocal[row] = fmaxf(0.f, lap - lan + MARGIN);
    }
}

// ---------------- kernel 4: deterministic means ----------------
__global__ void final_reduce(float* __restrict__ out, int out_size) {
    __shared__ float s1[256], s2[256];
    int t = threadIdx.x;
    float a = 0.f, b = 0.f;
    for (int i = t; i < N; i += 256) { a += g_rowLoss[i]; b += g_rowLocal[i]; }
    s1[t] = a; s2[t] = b;
    __syncthreads();
    for (int off = 128; off > 0; off >>= 1) {
        if (t < off) { s1[t] += s1[t + off]; s2[t] += s2[t + off]; }
        __syncthreads();
    }
    if (t == 0) {
        out[0] = s1[0] / (float)N;
        if (out_size > 1) out[1] = s2[0] / (float)N;
    }
}

// ---------------- launch ----------------
extern "C" void kernel_launch(void* const* d_in, const int* in_sizes, int n_in,
                              void* d_out, int out_size) {
    const float* X  = (const float*)d_in[0];
    const float* XL = (const float*)d_in[1];
    const int*   T  = (const int*)d_in[2];
    (void)in_sizes; (void)n_in;

    cudaFuncSetAttribute(gram_mma_kernel,
                         cudaFuncAttributeMaxDynamicSharedMemorySize, DYN_B);

    prep_targets<<<1, 1024>>>(T);
    convert_kernel<<<N, 256>>>(X);
    lnorms_kernel<<<N, 256>>>(XL);
    gram_mma_kernel<<<NBLK, 256, DYN_B>>>();
    finalize_rows<<<N / 8, 256>>>(X, XL);
    final_reduce<<<1, 256>>>((float*)d_out, out_size);
}